// round 5
// baseline (speedup 1.0000x reference)
#include <cuda_runtime.h>

#define NN 32768
#define GG 256
#define PP 128
#define EE 524288
#define HH 64
#define ROWS (GG*(PP-1))   // 32512

// ---- device scratch (no allocs allowed) ----
__device__ __align__(16) float g_h[NN*HH];     // ping buffer (8MB)
__device__ __align__(16) float g_m[NN*HH];     // pong buffer (8MB), holds final h
__device__ __align__(16) float g_Ag[GG*HH*HH]; // per-graph bilinear matrices (4MB)
__device__ __align__(16) float g_AB[HH*HH*2];  // packed fused weights [k][l]{a0,a1,b0,b1}
__device__ __align__(16) float g_c[HH];
__device__ int   g_is64;
// CSR
__device__ __align__(16) int g_cur[NN];
__device__ __align__(16) int g_off[NN + 4];
__device__ int g_srcl[EE];

// ---- f32x2 helpers ----
__device__ __forceinline__ unsigned long long pk2(float x, float y) {
    unsigned long long r; asm("mov.b64 %0,{%1,%2};" : "=l"(r) : "f"(x), "f"(y)); return r;
}
__device__ __forceinline__ unsigned long long ff2(unsigned long long a, unsigned long long b,
                                                  unsigned long long c) {
    unsigned long long d;
    asm("fma.rn.f32x2 %0,%1,%2,%3;" : "=l"(d) : "l"(a), "l"(b), "l"(c)); return d;
}
__device__ __forceinline__ float2 up2(unsigned long long a) {
    float x, y; asm("mov.b64 {%0,%1},%2;" : "=f"(x), "=f"(y) : "l"(a));
    return make_float2(x, y);
}

// ---- fused: precompute weights (blocks 0-15), bias+zero cursors (block 16), input layer (17+) ----
__global__ void k_pi(const float* __restrict__ x, const float* __restrict__ W1,
                     const float* __restrict__ b1,
                     const float* __restrict__ W2, const float* __restrict__ b2,
                     const float* __restrict__ W3, const float* __restrict__ b3,
                     const float* __restrict__ W4, const float* __restrict__ b4) {
    int tid = threadIdx.x;
    if (blockIdx.x < 16) {
        int e = blockIdx.x * 256 + tid;  // 4096 (o,k) entries
        int o = e >> 6, k = e & 63;
        float a = 0.f, b = 0.f;
        for (int t = 0; t < 64; ++t) {
            a += W4[o*128 + t]      * W3[t*64 + k];
            b += W4[o*128 + 64 + t] * W2[t*64 + k];
        }
        g_AB[k*128 + (o >> 1)*4 + (o & 1)]     = a;
        g_AB[k*128 + (o >> 1)*4 + 2 + (o & 1)] = b;
        return;
    }
    if (blockIdx.x == 16) {
        if (tid < 64) {
            float c = b4[tid];
            for (int t = 0; t < 64; ++t)
                c += W4[tid*128 + t]*b3[t] + W4[tid*128 + 64 + t]*b2[t];
            g_c[tid] = c;
        }
        int4 z = make_int4(0, 0, 0, 0);
        for (int i = tid; i < NN/4; i += 256) ((int4*)g_cur)[i] = z;
        return;
    }
    // ---- input layer part ----
    __shared__ __align__(16) float sW[8*64];
    __shared__ float sb[64];
    for (int e = tid; e < 512; e += 256) {
        int o = e >> 3, j = e & 7;
        sW[j*64 + o] = W1[e];
    }
    if (tid < 64) sb[tid] = b1[tid];
    __syncthreads();
    int lane = tid & 31, warp = tid >> 5;
    for (int node = (blockIdx.x - 17)*8 + warp; node < NN; node += 512*8) {
        float xv = (lane < 8) ? x[node*8 + lane] : 0.f;
        float a0 = sb[2*lane], a1 = sb[2*lane + 1];
        #pragma unroll
        for (int j = 0; j < 8; ++j) {
            float xj = __shfl_sync(0xffffffffu, xv, j);
            a0 += sW[j*64 + 2*lane]     * xj;
            a1 += sW[j*64 + 2*lane + 1] * xj;
        }
        a0 = fmaxf(a0, 0.f); a1 = fmaxf(a1, 0.f);
        float s = a0*a0 + a1*a1;
        #pragma unroll
        for (int off = 16; off; off >>= 1) s += __shfl_xor_sync(0xffffffffu, s, off);
        float rn = rsqrtf(s);
        ((float2*)g_h)[node*32 + lane] = make_float2(a0*rn, a1*rn);
    }
}

// ---- fused detect + histogram ----
__global__ void k_hd(const void* __restrict__ ei) {
    const int* ei32 = (const int*)ei;
    int tid = threadIdx.x;
    int bad = 0;
    for (int i = tid; i < 2048; i += 256) bad |= (ei32[2*i + 1] != 0);
    int any = __syncthreads_or(bad);
    int is64 = !any;
    if (blockIdx.x == 0 && tid == 0) g_is64 = is64;
    int e = blockIdx.x*256 + tid;
    int dst = is64 ? (int)((const long long*)ei)[EE + e] : ei32[EE + e];
    atomicAdd(&g_cur[dst], 1);
}

__global__ void k_scan() {   // 1 block, 1024 threads, coalesced int4, 8 chunks
    __shared__ int wsum[32];
    int tid = threadIdx.x, lane = tid & 31, wid = tid >> 5;
    int running = 0;
    for (int c = 0; c < 8; ++c) {
        int4 v = ((const int4*)g_cur)[c*1024 + tid];
        int s = v.x + v.y + v.z + v.w;
        int ss = s;
        #pragma unroll
        for (int o = 1; o < 32; o <<= 1) {
            int t = __shfl_up_sync(0xffffffffu, ss, o);
            if (lane >= o) ss += t;
        }
        if (lane == 31) wsum[wid] = ss;
        __syncthreads();
        if (wid == 0) {
            int w = wsum[lane];
            #pragma unroll
            for (int o = 1; o < 32; o <<= 1) {
                int t = __shfl_up_sync(0xffffffffu, w, o);
                if (lane >= o) w += t;
            }
            wsum[lane] = w;
        }
        __syncthreads();
        int base = running + (wid ? wsum[wid - 1] : 0) + ss - s;
        int4 o4; o4.x = base; o4.y = base + v.x; o4.z = o4.y + v.y; o4.w = o4.z + v.z;
        ((int4*)g_off)[c*1024 + tid] = o4;
        ((int4*)g_cur)[c*1024 + tid] = o4;
        running += wsum[31];
        __syncthreads();
    }
    if (tid == 0) g_off[NN] = EE;
}

__global__ void k_fill(const void* __restrict__ ei) {
    int e = blockIdx.x*256 + threadIdx.x;
    int src, dst;
    if (g_is64) {
        const long long* p = (const long long*)ei;
        src = (int)p[e]; dst = (int)p[EE + e];
    } else {
        const int* p = (const int*)ei;
        src = p[e]; dst = p[EE + e];
    }
    int pos = atomicAdd(&g_cur[dst], 1);
    g_srcl[pos] = src;
}

// ---- fused gather + update (f32x2, 4 accumulator chains) ----
__global__ void k_gup(const float* __restrict__ hin, float* __restrict__ hout) {
    __shared__ __align__(16) float4 sAB[2048];
    __shared__ __align__(16) unsigned long long sc[32];
    __shared__ float2 smh[8][64];
    int tid = threadIdx.x;
    for (int e = tid; e < 2048; e += 256) sAB[e] = ((const float4*)g_AB)[e];
    if (tid < 32) sc[tid] = ((const unsigned long long*)g_c)[tid];
    __syncthreads();
    int lane = tid & 31, warp = tid >> 5;
    const ulonglong2* wAB = (const ulonglong2*)sAB;
    for (int node = blockIdx.x*8 + warp; node < NN; node += gridDim.x*8) {
        int o0 = g_off[node], o1 = g_off[node + 1];
        float m_lo0 = 0.f, m_hi0 = 0.f, m_lo1 = 0.f, m_hi1 = 0.f;
        for (int b = o0; b < o1; b += 32) {
            int n = o1 - b; n = n > 32 ? 32 : n;
            int idx = (lane < n) ? g_srcl[b + lane] : 0;
            int j = 0;
            for (; j + 2 <= n; j += 2) {
                int s0 = __shfl_sync(0xffffffffu, idx, j);
                int s1 = __shfl_sync(0xffffffffu, idx, j + 1);
                m_lo0 += hin[s0*64 + lane];
                m_hi0 += hin[s0*64 + 32 + lane];
                m_lo1 += hin[s1*64 + lane];
                m_hi1 += hin[s1*64 + 32 + lane];
            }
            if (j < n) {
                int s0 = __shfl_sync(0xffffffffu, idx, j);
                m_lo0 += hin[s0*64 + lane];
                m_hi0 += hin[s0*64 + 32 + lane];
            }
        }
        float m_lo = m_lo0 + m_lo1, m_hi = m_hi0 + m_hi1;
        float h_lo = hin[node*64 + lane], h_hi = hin[node*64 + 32 + lane];
        smh[warp][lane]      = make_float2(m_lo, h_lo);
        smh[warp][32 + lane] = make_float2(m_hi, h_hi);
        __syncwarp();
        unsigned long long a00 = sc[lane], a01 = 0ULL, a10 = 0ULL, a11 = 0ULL;
        #pragma unroll 8
        for (int k = 0; k < 64; k += 2) {
            ulonglong2 w0 = wAB[k*32 + lane];
            ulonglong2 w1 = wAB[(k + 1)*32 + lane];
            float2 mh0 = smh[warp][k];
            float2 mh1 = smh[warp][k + 1];
            a00 = ff2(w0.x, pk2(mh0.x, mh0.x), a00);
            a01 = ff2(w0.y, pk2(mh0.y, mh0.y), a01);
            a10 = ff2(w1.x, pk2(mh1.x, mh1.x), a10);
            a11 = ff2(w1.y, pk2(mh1.y, mh1.y), a11);
        }
        __syncwarp();
        float2 p0 = up2(a00), p1 = up2(a01), p2 = up2(a10), p3 = up2(a11);
        float a0 = (p0.x + p1.x) + (p2.x + p3.x);
        float a1 = (p0.y + p1.y) + (p2.y + p3.y);
        a0 = fmaxf(a0, 0.f); a1 = fmaxf(a1, 0.f);
        float s = a0*a0 + a1*a1;
        #pragma unroll
        for (int off = 16; off; off >>= 1) s += __shfl_xor_sync(0xffffffffu, s, off);
        float rn = rsqrtf(s);
        ((float2*)hout)[node*32 + lane] = make_float2(a0*rn, a1*rn);
    }
}

// ---- Ag[g][o][i] = sum_j W5[o][i*64+j] * last[g][j]; block per o ----
__global__ void k_ag(const float* __restrict__ W5, const float* __restrict__ hfin) {
    __shared__ __align__(16) float sWT[64*64];  // [j][i]
    int o = blockIdx.x, tid = threadIdx.x;
    for (int e = tid; e < 4096; e += 256) {
        int j = e >> 6, i = e & 63;
        sWT[j*64 + i] = W5[o*4096 + i*64 + j];
    }
    __syncthreads();
    int lane = tid & 31, warp = tid >> 5;
    const unsigned long long* wp = (const unsigned long long*)sWT;
    for (int g = warp; g < GG; g += 8) {
        const float* lp = hfin + (g*128 + 127)*64;
        float l_lo = lp[lane], l_hi = lp[32 + lane];
        unsigned long long acc0 = 0, acc1 = 0;
        #pragma unroll
        for (int j = 0; j < 32; j += 2) {
            float ja = __shfl_sync(0xffffffffu, l_lo, j);
            float jb = __shfl_sync(0xffffffffu, l_lo, j + 1);
            acc0 = ff2(wp[j*32 + lane], pk2(ja, ja), acc0);
            acc1 = ff2(wp[(j + 1)*32 + lane], pk2(jb, jb), acc1);
        }
        #pragma unroll
        for (int j = 0; j < 32; j += 2) {
            float ja = __shfl_sync(0xffffffffu, l_hi, j);
            float jb = __shfl_sync(0xffffffffu, l_hi, j + 1);
            acc0 = ff2(wp[(j + 32)*32 + lane], pk2(ja, ja), acc0);
            acc1 = ff2(wp[(j + 33)*32 + lane], pk2(jb, jb), acc1);
        }
        float2 r0 = up2(acc0), r1 = up2(acc1);
        ((float2*)(g_Ag + g*4096 + o*64))[lane] = make_float2(r0.x + r1.x, r0.y + r1.y);
    }
}

// ---- fused y1 + head, one block per graph (dynamic smem: 16K Ag + 32K Wd1 + bufs) ----
__global__ void k_y1h(const float* __restrict__ hfin, const float* __restrict__ b5,
                      const float* __restrict__ Wd1, const float* __restrict__ bd1,
                      const float* __restrict__ Wd2, const float* __restrict__ bd2,
                      float* __restrict__ out) {
    extern __shared__ __align__(16) float dyn[];
    float* sAgT  = dyn;               // 64*64 [i][o]
    float* sW1T  = dyn + 4096;        // 64*128 [k][j]
    float* sb5   = dyn + 4096 + 8192;       // 64
    float* sb1   = sb5 + 64;                // 128
    float* sW2   = sb1 + 128;               // 128
    float* smbuf = sW2 + 128;               // 8 warps * 64
    int g = blockIdx.x, tid = threadIdx.x;
    for (int e = tid; e < 4096; e += 256) {
        int o = e & 63, i = e >> 6;
        sAgT[i*64 + o] = g_Ag[g*4096 + o*64 + i];
    }
    for (int e = tid; e < 8192; e += 256) {
        int j = e >> 6, k = e & 63;
        sW1T[k*128 + j] = Wd1[e];
    }
    if (tid < 64) sb5[tid] = b5[tid];
    if (tid < 128) { sb1[tid] = bd1[tid]; sW2[tid] = Wd2[tid]; }
    __syncthreads();
    float bias2 = bd2[0];
    int lane = tid & 31, warp = tid >> 5;
    float* smw = smbuf + warp*64;
    const unsigned long long* ap = (const unsigned long long*)sAgT;
    const ulonglong2* wp = (const ulonglong2*)sW1T;
    const unsigned long long* b5p = (const unsigned long long*)sb5;
    for (int p = warp; p < 127; p += 8) {
        // stage x row
        const float* xp = hfin + (g*128 + p)*64;
        smw[lane]      = xp[lane];
        smw[32 + lane] = xp[32 + lane];
        __syncwarp();
        // y = x @ Ag.T + b5   (lane holds outputs 2lane, 2lane+1)
        unsigned long long yacc0 = b5p[lane], yacc1 = 0ULL;
        #pragma unroll 8
        for (int i = 0; i < 64; i += 2) {
            float xi0 = smw[i], xi1 = smw[i + 1];
            yacc0 = ff2(ap[i*32 + lane], pk2(xi0, xi0), yacc0);
            yacc1 = ff2(ap[(i + 1)*32 + lane], pk2(xi1, xi1), yacc1);
        }
        __syncwarp();
        float2 y0 = up2(yacc0), y1v = up2(yacc1);
        ((float2*)smw)[lane] = make_float2(y0.x + y1v.x, y0.y + y1v.y);
        __syncwarp();
        // head: z = relu(y @ Wd1.T + b1); out = z @ w2
        unsigned long long z01 = pk2(sb1[4*lane], sb1[4*lane + 1]);
        unsigned long long z23 = pk2(sb1[4*lane + 2], sb1[4*lane + 3]);
        #pragma unroll 8
        for (int k = 0; k < 64; ++k) {
            float yk = smw[k];
            unsigned long long yy = pk2(yk, yk);
            ulonglong2 wv = wp[k*32 + lane];
            z01 = ff2(wv.x, yy, z01);
            z23 = ff2(wv.y, yy, z23);
        }
        __syncwarp();
        float2 za = up2(z01), zb = up2(z23);
        float4 w2 = *(float4*)&sW2[4*lane];
        float acc = fmaxf(za.x, 0.f)*w2.x + fmaxf(za.y, 0.f)*w2.y +
                    fmaxf(zb.x, 0.f)*w2.z + fmaxf(zb.y, 0.f)*w2.w;
        #pragma unroll
        for (int off = 16; off; off >>= 1) acc += __shfl_xor_sync(0xffffffffu, acc, off);
        if (lane == 0) out[g*127 + p] = acc + bias2;
    }
}

extern "C" void kernel_launch(void* const* d_in, const int* in_sizes, int n_in,
                              void* d_out, int out_size) {
    const float* x = (const float*)d_in[0];
    const void*  ei = d_in[1];
    int base = (in_sizes[3] == 1) ? 4 : 3;
    const float* W1  = (const float*)d_in[base + 0];
    const float* b1  = (const float*)d_in[base + 1];
    const float* W2  = (const float*)d_in[base + 2];
    const float* b2  = (const float*)d_in[base + 3];
    const float* W3  = (const float*)d_in[base + 4];
    const float* b3  = (const float*)d_in[base + 5];
    const float* W4  = (const float*)d_in[base + 6];
    const float* b4  = (const float*)d_in[base + 7];
    const float* W5  = (const float*)d_in[base + 8];
    const float* b5  = (const float*)d_in[base + 9];
    const float* Wd1 = (const float*)d_in[base + 10];
    const float* bd1 = (const float*)d_in[base + 11];
    const float* Wd2 = (const float*)d_in[base + 12];
    const float* bd2 = (const float*)d_in[base + 13];
    float* out = (float*)d_out;

    float *hA = nullptr, *hB = nullptr;
    cudaGetSymbolAddress((void**)&hA, g_h);
    cudaGetSymbolAddress((void**)&hB, g_m);

    static int smem_set = 0;
    if (!smem_set) {
        cudaFuncSetAttribute(k_y1h, cudaFuncAttributeMaxDynamicSharedMemorySize, 56*1024);
        smem_set = 1;
    }
    int y1h_smem = (4096 + 8192 + 64 + 128 + 128 + 8*64) * 4;

    k_pi<<<529, 256>>>(x, W1, b1, W2, b2, W3, b3, W4, b4);   // idx 0
    k_hd<<<EE/256, 256>>>(ei);                                // idx 1
    k_scan<<<1, 1024>>>();                                    // idx 2
    k_fill<<<EE/256, 256>>>(ei);                              // idx 3
    k_gup<<<512, 256>>>(hA, hB);                              // idx 4  <-- ncu capture slot
    k_gup<<<512, 256>>>(hB, hA);
    k_gup<<<512, 256>>>(hA, hB);
    k_ag<<<64, 256>>>(W5, hB);
    k_y1h<<<GG, 256, y1h_smem>>>(hB, b5, Wd1, bd1, Wd2, bd2, out);
}

// round 6
// speedup vs baseline: 1.0275x; 1.0275x over previous
#include <cuda_runtime.h>

#define NN 32768
#define GG 256
#define PP 128
#define EE 524288
#define HH 64
#define ROWS (GG*(PP-1))   // 32512

// ---- device scratch (no allocs allowed) ----
__device__ __align__(16) float g_h[NN*HH];     // ping buffer (8MB)
__device__ __align__(16) float g_m[NN*HH];     // pong buffer (8MB), holds final h
__device__ __align__(16) float g_Ag[GG*HH*HH]; // per-graph bilinear matrices (4MB)
__device__ __align__(16) float g_AB[HH*HH*2];  // packed fused weights [k][l]{a0,a1,b0,b1}
__device__ __align__(16) float g_c[HH];
__device__ int   g_is64;
// CSR
__device__ __align__(16) int g_cur[NN];
__device__ __align__(16) int g_off[NN + 4];
__device__ int g_srcl[EE];

// ---- f32x2 helpers ----
__device__ __forceinline__ unsigned long long pk2(float x, float y) {
    unsigned long long r; asm("mov.b64 %0,{%1,%2};" : "=l"(r) : "f"(x), "f"(y)); return r;
}
__device__ __forceinline__ unsigned long long ff2(unsigned long long a, unsigned long long b,
                                                  unsigned long long c) {
    unsigned long long d;
    asm("fma.rn.f32x2 %0,%1,%2,%3;" : "=l"(d) : "l"(a), "l"(b), "l"(c)); return d;
}
__device__ __forceinline__ float2 up2(unsigned long long a) {
    float x, y; asm("mov.b64 {%0,%1},%2;" : "=f"(x), "=f"(y) : "l"(a));
    return make_float2(x, y);
}

// ---- fused: weights (blocks 0-15), bias+cursors+detect (block 16), input layer (17+) ----
__global__ void k_pi(const float* __restrict__ x, const void* __restrict__ ei,
                     const float* __restrict__ W1, const float* __restrict__ b1,
                     const float* __restrict__ W2, const float* __restrict__ b2,
                     const float* __restrict__ W3, const float* __restrict__ b3,
                     const float* __restrict__ W4, const float* __restrict__ b4) {
    int tid = threadIdx.x;
    if (blockIdx.x < 16) {
        int e = blockIdx.x * 256 + tid;  // 4096 (o,k) entries
        int o = e >> 6, k = e & 63;
        float a = 0.f, b = 0.f;
        for (int t = 0; t < 64; ++t) {
            a += W4[o*128 + t]      * W3[t*64 + k];
            b += W4[o*128 + 64 + t] * W2[t*64 + k];
        }
        g_AB[k*128 + (o >> 1)*4 + (o & 1)]     = a;
        g_AB[k*128 + (o >> 1)*4 + 2 + (o & 1)] = b;
        return;
    }
    if (blockIdx.x == 16) {
        if (tid < 64) {
            float c = b4[tid];
            for (int t = 0; t < 64; ++t)
                c += W4[tid*128 + t]*b3[t] + W4[tid*128 + 64 + t]*b2[t];
            g_c[tid] = c;
        }
        int4 z = make_int4(0, 0, 0, 0);
        for (int i = tid; i < NN/4; i += 256) ((int4*)g_cur)[i] = z;
        // int64-vs-int32 detect (one block, once)
        const int* ei32 = (const int*)ei;
        int bad = 0;
        for (int i = tid; i < 2048; i += 256) bad |= (ei32[2*i + 1] != 0);
        int any = __syncthreads_or(bad);
        if (tid == 0) g_is64 = !any;
        return;
    }
    // ---- input layer part ----
    __shared__ __align__(16) float sW[8*64];
    __shared__ float sb[64];
    for (int e = tid; e < 512; e += 256) {
        int o = e >> 3, j = e & 7;
        sW[j*64 + o] = W1[e];
    }
    if (tid < 64) sb[tid] = b1[tid];
    __syncthreads();
    int lane = tid & 31, warp = tid >> 5;
    for (int node = (blockIdx.x - 17)*8 + warp; node < NN; node += 512*8) {
        float xv = (lane < 8) ? x[node*8 + lane] : 0.f;
        float a0 = sb[2*lane], a1 = sb[2*lane + 1];
        #pragma unroll
        for (int j = 0; j < 8; ++j) {
            float xj = __shfl_sync(0xffffffffu, xv, j);
            a0 += sW[j*64 + 2*lane]     * xj;
            a1 += sW[j*64 + 2*lane + 1] * xj;
        }
        a0 = fmaxf(a0, 0.f); a1 = fmaxf(a1, 0.f);
        float s = a0*a0 + a1*a1;
        #pragma unroll
        for (int off = 16; off; off >>= 1) s += __shfl_xor_sync(0xffffffffu, s, off);
        float rn = rsqrtf(s);
        ((float2*)g_h)[node*32 + lane] = make_float2(a0*rn, a1*rn);
    }
}

// ---- histogram (reads precomputed g_is64) ----
__global__ void k_hd(const void* __restrict__ ei) {
    int e = blockIdx.x*256 + threadIdx.x;
    int dst = g_is64 ? (int)((const long long*)ei)[EE + e] : ((const int*)ei)[EE + e];
    atomicAdd(&g_cur[dst], 1);
}

__global__ void k_scan() {   // 1 block, 1024 threads, coalesced int4, 8 chunks
    __shared__ int wsum[32];
    int tid = threadIdx.x, lane = tid & 31, wid = tid >> 5;
    int running = 0;
    for (int c = 0; c < 8; ++c) {
        int4 v = ((const int4*)g_cur)[c*1024 + tid];
        int s = v.x + v.y + v.z + v.w;
        int ss = s;
        #pragma unroll
        for (int o = 1; o < 32; o <<= 1) {
            int t = __shfl_up_sync(0xffffffffu, ss, o);
            if (lane >= o) ss += t;
        }
        if (lane == 31) wsum[wid] = ss;
        __syncthreads();
        if (wid == 0) {
            int w = wsum[lane];
            #pragma unroll
            for (int o = 1; o < 32; o <<= 1) {
                int t = __shfl_up_sync(0xffffffffu, w, o);
                if (lane >= o) w += t;
            }
            wsum[lane] = w;
        }
        __syncthreads();
        int base = running + (wid ? wsum[wid - 1] : 0) + ss - s;
        int4 o4; o4.x = base; o4.y = base + v.x; o4.z = o4.y + v.y; o4.w = o4.z + v.z;
        ((int4*)g_off)[c*1024 + tid] = o4;
        ((int4*)g_cur)[c*1024 + tid] = o4;
        running += wsum[31];
        __syncthreads();
    }
    if (tid == 0) g_off[NN] = EE;
}

__global__ void k_fill(const void* __restrict__ ei) {
    int e = blockIdx.x*256 + threadIdx.x;
    int src, dst;
    if (g_is64) {
        const long long* p = (const long long*)ei;
        src = (int)p[e]; dst = (int)p[EE + e];
    } else {
        const int* p = (const int*)ei;
        src = p[e]; dst = p[EE + e];
    }
    int pos = atomicAdd(&g_cur[dst], 1);
    g_srcl[pos] = src;
}

// ---- fused gather + update: 2 adjacent nodes per warp, high-MLP gather ----
__global__ void k_gup(const float* __restrict__ hin, float* __restrict__ hout) {
    __shared__ __align__(16) float4 sAB[2048];            // 32KB packed weights
    __shared__ __align__(16) float4 smh[8][2][64];        // 16KB (m,m,h,h) per warp/node/k
    int tid = threadIdx.x;
    for (int e = tid; e < 2048; e += 256) sAB[e] = ((const float4*)g_AB)[e];
    __syncthreads();
    int lane = tid & 31, warp = tid >> 5;
    const ulonglong2* wAB = (const ulonglong2*)sAB;
    unsigned long long cinit = ((const unsigned long long*)g_c)[lane];
    for (int pair = blockIdx.x*8 + warp; pair < NN/2; pair += gridDim.x*8) {
        int nA = pair*2;
        int oA0 = g_off[nA], oA1 = g_off[nA + 1], oB1 = g_off[nA + 2];
        int degA = oA1 - oA0, total = oB1 - oA0;
        float mA_lo = 0.f, mA_hi = 0.f, mB_lo = 0.f, mB_hi = 0.f;
        for (int b = 0; b < total; b += 32) {
            int n = total - b; if (n > 32) n = 32;
            int idx = (lane < n) ? g_srcl[oA0 + b + lane] : 0;
            #pragma unroll 8
            for (int j = 0; j < n; ++j) {
                int s = __shfl_sync(0xffffffffu, idx, j);
                float vlo = hin[s*64 + lane];
                float vhi = hin[s*64 + 32 + lane];
                if (b + j < degA) { mA_lo += vlo; mA_hi += vhi; }
                else              { mB_lo += vlo; mB_hi += vhi; }
            }
        }
        float hA_lo = hin[nA*64 + lane],      hA_hi = hin[nA*64 + 32 + lane];
        float hB_lo = hin[nA*64 + 64 + lane], hB_hi = hin[nA*64 + 96 + lane];
        smh[warp][0][lane]      = make_float4(mA_lo, mA_lo, hA_lo, hA_lo);
        smh[warp][0][32 + lane] = make_float4(mA_hi, mA_hi, hA_hi, hA_hi);
        smh[warp][1][lane]      = make_float4(mB_lo, mB_lo, hB_lo, hB_lo);
        smh[warp][1][32 + lane] = make_float4(mB_hi, mB_hi, hB_hi, hB_hi);
        __syncwarp();
        const ulonglong2* xA = (const ulonglong2*)smh[warp][0];
        const ulonglong2* xB = (const ulonglong2*)smh[warp][1];
        unsigned long long aA0 = cinit, aA1 = 0ULL, aB0 = cinit, aB1 = 0ULL;
        #pragma unroll 8
        for (int k = 0; k < 64; ++k) {
            ulonglong2 w = wAB[k*32 + lane];
            ulonglong2 vA = xA[k];
            ulonglong2 vB = xB[k];
            aA0 = ff2(w.x, vA.x, aA0);   // A-weights * m
            aA1 = ff2(w.y, vA.y, aA1);   // B-weights * h
            aB0 = ff2(w.x, vB.x, aB0);
            aB1 = ff2(w.y, vB.y, aB1);
        }
        __syncwarp();
        float2 pA0 = up2(aA0), pA1 = up2(aA1);
        float2 pB0 = up2(aB0), pB1 = up2(aB1);
        float a0 = fmaxf(pA0.x + pA1.x, 0.f), a1 = fmaxf(pA0.y + pA1.y, 0.f);
        float c0 = fmaxf(pB0.x + pB1.x, 0.f), c1 = fmaxf(pB0.y + pB1.y, 0.f);
        float sA = a0*a0 + a1*a1, sB = c0*c0 + c1*c1;
        #pragma unroll
        for (int off = 16; off; off >>= 1) {
            sA += __shfl_xor_sync(0xffffffffu, sA, off);
            sB += __shfl_xor_sync(0xffffffffu, sB, off);
        }
        float rA = rsqrtf(sA), rB = rsqrtf(sB);
        ((float2*)hout)[nA*32 + lane]      = make_float2(a0*rA, a1*rA);
        ((float2*)hout)[nA*32 + 32 + lane] = make_float2(c0*rB, c1*rB);
    }
}

// ---- Ag[g][o][i] = sum_j W5[o][i*64+j] * last[g][j]; block per o ----
__global__ void k_ag(const float* __restrict__ W5, const float* __restrict__ hfin) {
    __shared__ __align__(16) float sWT[64*64];  // [j][i]
    int o = blockIdx.x, tid = threadIdx.x;
    for (int e = tid; e < 4096; e += 256) {
        int j = e >> 6, i = e & 63;
        sWT[j*64 + i] = W5[o*4096 + i*64 + j];
    }
    __syncthreads();
    int lane = tid & 31, warp = tid >> 5;
    const unsigned long long* wp = (const unsigned long long*)sWT;
    for (int g = warp; g < GG; g += 8) {
        const float* lp = hfin + (g*128 + 127)*64;
        float l_lo = lp[lane], l_hi = lp[32 + lane];
        unsigned long long acc0 = 0, acc1 = 0;
        #pragma unroll
        for (int j = 0; j < 32; j += 2) {
            float ja = __shfl_sync(0xffffffffu, l_lo, j);
            float jb = __shfl_sync(0xffffffffu, l_lo, j + 1);
            acc0 = ff2(wp[j*32 + lane], pk2(ja, ja), acc0);
            acc1 = ff2(wp[(j + 1)*32 + lane], pk2(jb, jb), acc1);
        }
        #pragma unroll
        for (int j = 0; j < 32; j += 2) {
            float ja = __shfl_sync(0xffffffffu, l_hi, j);
            float jb = __shfl_sync(0xffffffffu, l_hi, j + 1);
            acc0 = ff2(wp[(j + 32)*32 + lane], pk2(ja, ja), acc0);
            acc1 = ff2(wp[(j + 33)*32 + lane], pk2(jb, jb), acc1);
        }
        float2 r0 = up2(acc0), r1 = up2(acc1);
        ((float2*)(g_Ag + g*4096 + o*64))[lane] = make_float2(r0.x + r1.x, r0.y + r1.y);
    }
}

// ---- fused y1 + head, one block per graph ----
__global__ void k_y1h(const float* __restrict__ hfin, const float* __restrict__ b5,
                      const float* __restrict__ Wd1, const float* __restrict__ bd1,
                      const float* __restrict__ Wd2, const float* __restrict__ bd2,
                      float* __restrict__ out) {
    extern __shared__ __align__(16) float dyn[];
    float* sAgT  = dyn;               // 64*64 [i][o]
    float* sW1T  = dyn + 4096;        // 64*128 [k][j]
    float* sb5   = dyn + 4096 + 8192;
    float* sb1   = sb5 + 64;
    float* sW2   = sb1 + 128;
    float* smbuf = sW2 + 128;         // 8 warps * 64
    int g = blockIdx.x, tid = threadIdx.x;
    for (int e = tid; e < 4096; e += 256) {
        int o = e & 63, i = e >> 6;
        sAgT[i*64 + o] = g_Ag[g*4096 + o*64 + i];
    }
    for (int e = tid; e < 8192; e += 256) {
        int j = e >> 6, k = e & 63;
        sW1T[k*128 + j] = Wd1[e];
    }
    if (tid < 64) sb5[tid] = b5[tid];
    if (tid < 128) { sb1[tid] = bd1[tid]; sW2[tid] = Wd2[tid]; }
    __syncthreads();
    float bias2 = bd2[0];
    int lane = tid & 31, warp = tid >> 5;
    float* smw = smbuf + warp*64;
    const unsigned long long* ap = (const unsigned long long*)sAgT;
    const ulonglong2* wp = (const ulonglong2*)sW1T;
    const unsigned long long* b5p = (const unsigned long long*)sb5;
    for (int p = warp; p < 127; p += 8) {
        const float* xp = hfin + (g*128 + p)*64;
        smw[lane]      = xp[lane];
        smw[32 + lane] = xp[32 + lane];
        __syncwarp();
        unsigned long long yacc0 = b5p[lane], yacc1 = 0ULL;
        #pragma unroll 8
        for (int i = 0; i < 64; i += 2) {
            float xi0 = smw[i], xi1 = smw[i + 1];
            yacc0 = ff2(ap[i*32 + lane], pk2(xi0, xi0), yacc0);
            yacc1 = ff2(ap[(i + 1)*32 + lane], pk2(xi1, xi1), yacc1);
        }
        __syncwarp();
        float2 y0 = up2(yacc0), y1v = up2(yacc1);
        ((float2*)smw)[lane] = make_float2(y0.x + y1v.x, y0.y + y1v.y);
        __syncwarp();
        unsigned long long z01 = pk2(sb1[4*lane], sb1[4*lane + 1]);
        unsigned long long z23 = pk2(sb1[4*lane + 2], sb1[4*lane + 3]);
        #pragma unroll 8
        for (int k = 0; k < 64; ++k) {
            float yk = smw[k];
            unsigned long long yy = pk2(yk, yk);
            ulonglong2 wv = wp[k*32 + lane];
            z01 = ff2(wv.x, yy, z01);
            z23 = ff2(wv.y, yy, z23);
        }
        __syncwarp();
        float2 za = up2(z01), zb = up2(z23);
        float4 w2 = *(float4*)&sW2[4*lane];
        float acc = fmaxf(za.x, 0.f)*w2.x + fmaxf(za.y, 0.f)*w2.y +
                    fmaxf(zb.x, 0.f)*w2.z + fmaxf(zb.y, 0.f)*w2.w;
        #pragma unroll
        for (int off = 16; off; off >>= 1) acc += __shfl_xor_sync(0xffffffffu, acc, off);
        if (lane == 0) out[g*127 + p] = acc + bias2;
    }
}

extern "C" void kernel_launch(void* const* d_in, const int* in_sizes, int n_in,
                              void* d_out, int out_size) {
    const float* x = (const float*)d_in[0];
    const void*  ei = d_in[1];
    int base = (in_sizes[3] == 1) ? 4 : 3;
    const float* W1  = (const float*)d_in[base + 0];
    const float* b1  = (const float*)d_in[base + 1];
    const float* W2  = (const float*)d_in[base + 2];
    const float* b2  = (const float*)d_in[base + 3];
    const float* W3  = (const float*)d_in[base + 4];
    const float* b3  = (const float*)d_in[base + 5];
    const float* W4  = (const float*)d_in[base + 6];
    const float* b4  = (const float*)d_in[base + 7];
    const float* W5  = (const float*)d_in[base + 8];
    const float* b5  = (const float*)d_in[base + 9];
    const float* Wd1 = (const float*)d_in[base + 10];
    const float* bd1 = (const float*)d_in[base + 11];
    const float* Wd2 = (const float*)d_in[base + 12];
    const float* bd2 = (const float*)d_in[base + 13];
    float* out = (float*)d_out;

    float *hA = nullptr, *hB = nullptr;
    cudaGetSymbolAddress((void**)&hA, g_h);
    cudaGetSymbolAddress((void**)&hB, g_m);

    static int smem_set = 0;
    if (!smem_set) {
        cudaFuncSetAttribute(k_y1h, cudaFuncAttributeMaxDynamicSharedMemorySize, 56*1024);
        smem_set = 1;
    }
    int y1h_smem = (4096 + 8192 + 64 + 128 + 128 + 8*64) * 4;

    k_pi<<<529, 256>>>(x, ei, W1, b1, W2, b2, W3, b3, W4, b4);
    k_hd<<<EE/256, 256>>>(ei);
    k_scan<<<1, 1024>>>();
    k_fill<<<EE/256, 256>>>(ei);
    k_gup<<<512, 256>>>(hA, hB);
    k_gup<<<512, 256>>>(hB, hA);
    k_gup<<<512, 256>>>(hA, hB);
    k_ag<<<64, 256>>>(W5, hB);
    k_y1h<<<GG, 256, y1h_smem>>>(hB, b5, Wd1, bd1, Wd2, bd2, out);
}

// round 7
// speedup vs baseline: 1.3079x; 1.2729x over previous
#include <cuda_runtime.h>

#define NN 32768
#define GG 256
#define PP 128
#define EE 524288
#define HH 64
#define CAP 96
#define ROWS (GG*(PP-1))

typedef unsigned long long ull;

// ---- device scratch ----
__device__ __align__(16) float g_h[(NN+1)*HH];   // +1 sentinel zero row
__device__ __align__(16) float g_m[(NN+1)*HH];
__device__ __align__(16) float g_Ag[GG*HH*HH];
__device__ __align__(16) float g_AB[HH*HH*2];    // [k][opair]{a0,a1,b0,b1}
__device__ __align__(16) float g_c[HH];
__device__ int   g_is64;
__device__ __align__(16) int g_deg[NN];          // zeroed at end of k_ag each replay
__device__ int g_srcl[NN*CAP];

// ---- f32x2 helpers ----
__device__ __forceinline__ ull pk2(float x, float y) {
    ull r; asm("mov.b64 %0,{%1,%2};" : "=l"(r) : "f"(x), "f"(y)); return r;
}
__device__ __forceinline__ ull ff2(ull a, ull b, ull c) {
    ull d; asm("fma.rn.f32x2 %0,%1,%2,%3;" : "=l"(d) : "l"(a), "l"(b), "l"(c)); return d;
}
__device__ __forceinline__ float2 up2(ull a) {
    float x, y; asm("mov.b64 {%0,%1},%2;" : "=f"(x), "=f"(y) : "l"(a));
    return make_float2(x, y);
}

// ---- launch 1: weights (blk 0-15), bias+detect+sentinel (blk 16), input layer (17+) ----
__global__ void k_pi(const float* __restrict__ x, const void* __restrict__ ei,
                     const float* __restrict__ W1, const float* __restrict__ b1,
                     const float* __restrict__ W2, const float* __restrict__ b2,
                     const float* __restrict__ W3, const float* __restrict__ b3,
                     const float* __restrict__ W4, const float* __restrict__ b4) {
    int tid = threadIdx.x;
    if (blockIdx.x < 16) {
        int e = blockIdx.x * 256 + tid;
        int o = e >> 6, k = e & 63;
        float a = 0.f, b = 0.f;
        for (int t = 0; t < 64; ++t) {
            a += W4[o*128 + t]      * W3[t*64 + k];
            b += W4[o*128 + 64 + t] * W2[t*64 + k];
        }
        g_AB[k*128 + (o >> 1)*4 + (o & 1)]     = a;
        g_AB[k*128 + (o >> 1)*4 + 2 + (o & 1)] = b;
        return;
    }
    if (blockIdx.x == 16) {
        if (tid < 64) {
            float c = b4[tid];
            for (int t = 0; t < 64; ++t)
                c += W4[tid*128 + t]*b3[t] + W4[tid*128 + 64 + t]*b2[t];
            g_c[tid] = c;
            g_h[NN*64 + tid] = 0.f;   // sentinel rows
            g_m[NN*64 + tid] = 0.f;
        }
        const int* ei32 = (const int*)ei;
        int bad = 0;
        for (int i = tid; i < 2048; i += 256) bad |= (ei32[2*i + 1] != 0);
        int any = __syncthreads_or(bad);
        if (tid == 0) g_is64 = !any;
        return;
    }
    __shared__ __align__(16) float sW[8*64];
    __shared__ float sb[64];
    for (int e = tid; e < 512; e += 256) {
        int o = e >> 3, j = e & 7;
        sW[j*64 + o] = W1[e];
    }
    if (tid < 64) sb[tid] = b1[tid];
    __syncthreads();
    int lane = tid & 31, warp = tid >> 5;
    for (int node = (blockIdx.x - 17)*8 + warp; node < NN; node += 512*8) {
        float xv = (lane < 8) ? x[node*8 + lane] : 0.f;
        float a0 = sb[2*lane], a1 = sb[2*lane + 1];
        #pragma unroll
        for (int j = 0; j < 8; ++j) {
            float xj = __shfl_sync(0xffffffffu, xv, j);
            a0 += sW[j*64 + 2*lane]     * xj;
            a1 += sW[j*64 + 2*lane + 1] * xj;
        }
        a0 = fmaxf(a0, 0.f); a1 = fmaxf(a1, 0.f);
        float s = a0*a0 + a1*a1;
        #pragma unroll
        for (int off = 16; off; off >>= 1) s += __shfl_xor_sync(0xffffffffu, s, off);
        float rn = rsqrtf(s);
        ((float2*)g_h)[node*32 + lane] = make_float2(a0*rn, a1*rn);
    }
}

// ---- launch 2: direct bucket CSR fill ----
__global__ void k_fill2(const void* __restrict__ ei) {
    int e = blockIdx.x*256 + threadIdx.x;
    int src, dst;
    if (g_is64) {
        const long long* p = (const long long*)ei;
        src = (int)p[e]; dst = (int)p[EE + e];
    } else {
        const int* p = (const int*)ei;
        src = p[e]; dst = p[EE + e];
    }
    int pos = atomicAdd(&g_deg[dst], 1);
    g_srcl[dst*CAP + pos] = src;
}

// ---- launches 3-5: gather + update, 8 nodes/warp, weight-amortized GEMM ----
__global__ void k_gup(const float* __restrict__ hin, float* __restrict__ hout) {
    extern __shared__ __align__(16) float4 dynsm[];
    float4* sW = dynsm;          // 2048 float4 = 32KB
    float4* sX = dynsm + 2048;   // 8 warps * 8 nodes * 64 k = 4096 float4 = 64KB
    int tid = threadIdx.x;
    for (int e = tid; e < 2048; e += 256) sW[e] = ((const float4*)g_AB)[e];
    __syncthreads();
    int lane = tid & 31, warp = tid >> 5;
    float4* myX = sX + warp*512;
    ull cinit = ((const ull*)g_c)[lane];
    int nb = blockIdx.x*64 + warp*8;
    // gather phase
    #pragma unroll 2
    for (int t = 0; t < 8; ++t) {
        int node = nb + t;
        int deg = g_deg[node];
        const int* sl = g_srcl + node*CAP;
        float2 m = make_float2(0.f, 0.f);
        for (int b = 0; b < deg; b += 32) {
            int n = deg - b; if (n > 32) n = 32;
            int idx = (lane < n) ? sl[b + lane] : NN;   // sentinel -> zero row
            int nr = (n + 7) & ~7;
            #pragma unroll 8
            for (int j = 0; j < nr; ++j) {
                int s = __shfl_sync(0xffffffffu, idx, j);
                float2 v = ((const float2*)hin)[s*32 + lane];
                m.x += v.x; m.y += v.y;
            }
        }
        float2 h = ((const float2*)hin)[node*32 + lane];
        myX[t*64 + 2*lane]     = make_float4(m.x, m.x, h.x, h.x);
        myX[t*64 + 2*lane + 1] = make_float4(m.y, m.y, h.y, h.y);
    }
    __syncwarp();
    // GEMM phase: 8 nodes share each weight load
    ull aA[8], aB[8];
    #pragma unroll
    for (int t = 0; t < 8; ++t) { aA[t] = cinit; aB[t] = 0ULL; }
    const ulonglong2* wp = (const ulonglong2*)sW;
    const ulonglong2* xp = (const ulonglong2*)myX;
    #pragma unroll 2
    for (int k = 0; k < 64; ++k) {
        ulonglong2 w = wp[k*32 + lane];
        #pragma unroll
        for (int t = 0; t < 8; ++t) {
            ulonglong2 v = xp[t*64 + k];   // broadcast load
            aA[t] = ff2(w.x, v.x, aA[t]);
            aB[t] = ff2(w.y, v.y, aB[t]);
        }
    }
    // epilogue
    #pragma unroll
    for (int t = 0; t < 8; ++t) {
        float2 pa = up2(aA[t]), pb = up2(aB[t]);
        float a0 = fmaxf(pa.x + pb.x, 0.f), a1 = fmaxf(pa.y + pb.y, 0.f);
        float s = a0*a0 + a1*a1;
        #pragma unroll
        for (int off = 16; off; off >>= 1) s += __shfl_xor_sync(0xffffffffu, s, off);
        float rn = rsqrtf(s);
        ((float2*)hout)[(nb + t)*32 + lane] = make_float2(a0*rn, a1*rn);
    }
}

// ---- launch 6: Ag, 256 blocks (o x graph-chunk), 4 graphs/warp/pass; also zero g_deg ----
__global__ void k_ag(const float* __restrict__ W5, const float* __restrict__ hfin) {
    __shared__ __align__(16) float sWT[4096];     // [j][i]
    __shared__ __align__(16) float2 sL[8][4][64];
    int bi = blockIdx.x, tid = threadIdx.x;
    int o = bi >> 2, gc = bi & 3;
    if (tid < 128) g_deg[bi*128 + tid] = 0;       // reset cursors for next replay
    for (int e = tid; e < 4096; e += 256) {
        int i = e >> 6, j = e & 63;
        sWT[j*64 + i] = W5[o*4096 + e];
    }
    __syncthreads();
    int lane = tid & 31, warp = tid >> 5;
    const ull* wp = (const ull*)sWT;
    for (int pass = 0; pass < 2; ++pass) {
        int gbase = gc*64 + pass*32 + warp*4;
        #pragma unroll
        for (int t = 0; t < 4; ++t) {
            int g = gbase + t;
            float2 v = ((const float2*)hfin)[(g*128 + 127)*32 + lane];
            sL[warp][t][2*lane]     = make_float2(v.x, v.x);
            sL[warp][t][2*lane + 1] = make_float2(v.y, v.y);
        }
        __syncwarp();
        ull acc[4] = {0ULL, 0ULL, 0ULL, 0ULL};
        #pragma unroll 2
        for (int j = 0; j < 64; ++j) {
            ull w = wp[j*32 + lane];
            #pragma unroll
            for (int t = 0; t < 4; ++t) {
                ull xv = *(const ull*)&sL[warp][t][j];
                acc[t] = ff2(w, xv, acc[t]);
            }
        }
        __syncwarp();
        #pragma unroll
        for (int t = 0; t < 4; ++t) {
            int g = gbase + t;
            ((float2*)(g_Ag + g*4096 + o*64))[lane] = up2(acc[t]);
        }
    }
}

// ---- launch 7: fused y1 + head, 4 rows/warp/pass ----
__global__ void k_y1h(const float* __restrict__ hfin, const float* __restrict__ b5,
                      const float* __restrict__ Wd1, const float* __restrict__ bd1,
                      const float* __restrict__ Wd2, const float* __restrict__ bd2,
                      float* __restrict__ out) {
    extern __shared__ __align__(16) float dyn[];
    float*  sAgT = dyn;                   // 4096 [i][o]
    float*  sW1T = dyn + 4096;            // 8192 [k][j]
    float2* sY   = (float2*)(dyn + 4096 + 8192);  // 8*4*64 float2 = 2048 floats
    float*  sb5  = dyn + 4096 + 8192 + 4096;
    float*  sb1  = sb5 + 64;
    float*  sW2  = sb1 + 128;
    int g = blockIdx.x, tid = threadIdx.x;
    for (int e = tid; e < 4096; e += 256) {
        int o = e & 63, i = e >> 6;
        sAgT[i*64 + o] = g_Ag[g*4096 + o*64 + i];
    }
    for (int e = tid; e < 8192; e += 256) {
        int j = e >> 6, k = e & 63;
        sW1T[k*128 + j] = Wd1[e];
    }
    if (tid < 64) sb5[tid] = b5[tid];
    if (tid < 128) { sb1[tid] = bd1[tid]; sW2[tid] = Wd2[tid]; }
    __syncthreads();
    float bias2 = bd2[0];
    int lane = tid & 31, warp = tid >> 5;
    float2 (*sy)[64] = (float2 (*)[64])(sY + warp*256);
    const ull* ap = (const ull*)sAgT;
    const ulonglong2* wp = (const ulonglong2*)sW1T;
    const ull* b5p = (const ull*)sb5;
    for (int pass = 0; pass < 4; ++pass) {
        int rbase = pass*32 + warp*4;
        #pragma unroll
        for (int t = 0; t < 4; ++t) {
            int r = rbase + t;
            float2 v = (r < 127) ? ((const float2*)hfin)[(g*128 + r)*32 + lane]
                                 : make_float2(0.f, 0.f);
            sy[t][2*lane]     = make_float2(v.x, v.x);
            sy[t][2*lane + 1] = make_float2(v.y, v.y);
        }
        __syncwarp();
        ull ya[4];
        #pragma unroll
        for (int t = 0; t < 4; ++t) ya[t] = b5p[lane];
        #pragma unroll 2
        for (int i = 0; i < 64; ++i) {
            ull a = ap[i*32 + lane];
            #pragma unroll
            for (int t = 0; t < 4; ++t) {
                ull xv = *(const ull*)&sy[t][i];
                ya[t] = ff2(a, xv, ya[t]);
            }
        }
        __syncwarp();
        #pragma unroll
        for (int t = 0; t < 4; ++t) {
            float2 y = up2(ya[t]);
            sy[t][2*lane]     = make_float2(y.x, y.x);
            sy[t][2*lane + 1] = make_float2(y.y, y.y);
        }
        __syncwarp();
        ull z01[4], z23[4];
        #pragma unroll
        for (int t = 0; t < 4; ++t) {
            z01[t] = pk2(sb1[4*lane], sb1[4*lane + 1]);
            z23[t] = pk2(sb1[4*lane + 2], sb1[4*lane + 3]);
        }
        #pragma unroll 2
        for (int k = 0; k < 64; ++k) {
            ulonglong2 wv = wp[k*32 + lane];
            #pragma unroll
            for (int t = 0; t < 4; ++t) {
                ull yy = *(const ull*)&sy[t][k];
                z01[t] = ff2(wv.x, yy, z01[t]);
                z23[t] = ff2(wv.y, yy, z23[t]);
            }
        }
        __syncwarp();
        float4 w2 = *(float4*)&sW2[4*lane];
        #pragma unroll
        for (int t = 0; t < 4; ++t) {
            float2 za = up2(z01[t]), zb = up2(z23[t]);
            float acc = fmaxf(za.x, 0.f)*w2.x + fmaxf(za.y, 0.f)*w2.y +
                        fmaxf(zb.x, 0.f)*w2.z + fmaxf(zb.y, 0.f)*w2.w;
            #pragma unroll
            for (int off = 16; off; off >>= 1)
                acc += __shfl_xor_sync(0xffffffffu, acc, off);
            int r = rbase + t;
            if (lane == 0 && r < 127) out[g*127 + r] = acc + bias2;
        }
    }
}

extern "C" void kernel_launch(void* const* d_in, const int* in_sizes, int n_in,
                              void* d_out, int out_size) {
    const float* x = (const float*)d_in[0];
    const void*  ei = d_in[1];
    int base = (in_sizes[3] == 1) ? 4 : 3;
    const float* W1  = (const float*)d_in[base + 0];
    const float* b1  = (const float*)d_in[base + 1];
    const float* W2  = (const float*)d_in[base + 2];
    const float* b2  = (const float*)d_in[base + 3];
    const float* W3  = (const float*)d_in[base + 4];
    const float* b3  = (const float*)d_in[base + 5];
    const float* W4  = (const float*)d_in[base + 6];
    const float* b4  = (const float*)d_in[base + 7];
    const float* W5  = (const float*)d_in[base + 8];
    const float* b5  = (const float*)d_in[base + 9];
    const float* Wd1 = (const float*)d_in[base + 10];
    const float* bd1 = (const float*)d_in[base + 11];
    const float* Wd2 = (const float*)d_in[base + 12];
    const float* bd2 = (const float*)d_in[base + 13];
    float* out = (float*)d_out;

    float *hA = nullptr, *hB = nullptr;
    cudaGetSymbolAddress((void**)&hA, g_h);
    cudaGetSymbolAddress((void**)&hB, g_m);

    static int smem_set = 0;
    if (!smem_set) {
        cudaFuncSetAttribute(k_gup, cudaFuncAttributeMaxDynamicSharedMemorySize, 96*1024);
        cudaFuncSetAttribute(k_y1h, cudaFuncAttributeMaxDynamicSharedMemorySize, 72*1024);
        smem_set = 1;
    }
    int gup_smem = (2048 + 4096) * 16;                       // 96KB
    int y1h_smem = (4096 + 8192 + 4096 + 64 + 128 + 128) * 4; // ~66KB

    k_pi<<<529, 256>>>(x, ei, W1, b1, W2, b2, W3, b3, W4, b4);  // launch 1
    k_fill2<<<EE/256, 256>>>(ei);                                // launch 2
    k_gup<<<NN/64, 256, gup_smem>>>(hA, hB);                     // launch 3
    k_gup<<<NN/64, 256, gup_smem>>>(hB, hA);                     // launch 4 <- ncu capture
    k_gup<<<NN/64, 256, gup_smem>>>(hA, hB);                     // launch 5
    k_ag<<<256, 256>>>(W5, hB);                                  // launch 6
    k_y1h<<<GG, 256, y1h_smem>>>(hB, b5, Wd1, bd1, Wd2, bd2, out); // launch 7
}

// round 9
// speedup vs baseline: 1.7760x; 1.3579x over previous
#include <cuda_runtime.h>

#define NN 32768
#define GG 256
#define PP 128
#define EE 524288
#define HH 64
#define CAP 96
#define ROWS (GG*(PP-1))

typedef unsigned long long ull;

// ---- device scratch ----
__device__ __align__(16) float g_h[(NN+1)*HH];   // +1 sentinel zero row
__device__ __align__(16) float g_m[(NN+1)*HH];
__device__ __align__(16) float g_Ag[GG*HH*HH];
__device__ __align__(16) float g_AB[HH*HH*2];    // A table [0,4096), B table [4096,8192), k-pair packed
__device__ __align__(16) float g_c[HH];
__device__ int   g_is64;
__device__ __align__(16) int g_deg[NN];          // zeroed at end of k_ag each replay
__device__ int g_srcl[NN*CAP];

// ---- f32x2 helpers ----
__device__ __forceinline__ ull pk2(float x, float y) {
    ull r; asm("mov.b64 %0,{%1,%2};" : "=l"(r) : "f"(x), "f"(y)); return r;
}
__device__ __forceinline__ ull ff2(ull a, ull b, ull c) {
    ull d; asm("fma.rn.f32x2 %0,%1,%2,%3;" : "=l"(d) : "l"(a), "l"(b), "l"(c)); return d;
}
__device__ __forceinline__ float2 up2(ull a) {
    float x, y; asm("mov.b64 {%0,%1},%2;" : "=f"(x), "=f"(y) : "l"(a));
    return make_float2(x, y);
}

// ---- launch 1: weights (blk 0-15), bias+detect+sentinel (blk 16), input layer (17+) ----
__global__ void k_pi(const float* __restrict__ x, const void* __restrict__ ei,
                     const float* __restrict__ W1, const float* __restrict__ b1,
                     const float* __restrict__ W2, const float* __restrict__ b2,
                     const float* __restrict__ W3, const float* __restrict__ b3,
                     const float* __restrict__ W4, const float* __restrict__ b4) {
    int tid = threadIdx.x;
    if (blockIdx.x < 16) {
        int e = blockIdx.x * 256 + tid;
        int o = e >> 6, k = e & 63;
        float a = 0.f, b = 0.f;
        for (int t = 0; t < 64; ++t) {
            a += W4[o*128 + t]      * W3[t*64 + k];
            b += W4[o*128 + 64 + t] * W2[t*64 + k];
        }
        // k-pair packed: float4 at (kp*32 + (o&31)) holds {X[o][2kp],X[o][2kp+1],X[o+32][2kp],X[o+32][2kp+1]}
        int kp = k >> 1, ob = o & 31, comp = ((o >> 5) << 1) | (k & 1);
        g_AB[(kp*32 + ob)*4 + comp]        = a;
        g_AB[4096 + (kp*32 + ob)*4 + comp] = b;
        return;
    }
    if (blockIdx.x == 16) {
        if (tid < 64) {
            float c = b4[tid];
            for (int t = 0; t < 64; ++t)
                c += W4[tid*128 + t]*b3[t] + W4[tid*128 + 64 + t]*b2[t];
            g_c[tid] = c;
            g_h[NN*64 + tid] = 0.f;   // sentinel rows
            g_m[NN*64 + tid] = 0.f;
        }
        const int* ei32 = (const int*)ei;
        int bad = 0;
        for (int i = tid; i < 2048; i += 256) bad |= (ei32[2*i + 1] != 0);
        int any = __syncthreads_or(bad);
        if (tid == 0) g_is64 = !any;
        return;
    }
    __shared__ __align__(16) float sW[8*64];
    __shared__ float sb[64];
    for (int e = tid; e < 512; e += 256) {
        int o = e >> 3, j = e & 7;
        sW[j*64 + o] = W1[e];
    }
    if (tid < 64) sb[tid] = b1[tid];
    __syncthreads();
    int lane = tid & 31, warp = tid >> 5;
    for (int node = (blockIdx.x - 17)*8 + warp; node < NN; node += 512*8) {
        float xv = (lane < 8) ? x[node*8 + lane] : 0.f;
        float a0 = sb[2*lane], a1 = sb[2*lane + 1];
        #pragma unroll
        for (int j = 0; j < 8; ++j) {
            float xj = __shfl_sync(0xffffffffu, xv, j);
            a0 += sW[j*64 + 2*lane]     * xj;
            a1 += sW[j*64 + 2*lane + 1] * xj;
        }
        a0 = fmaxf(a0, 0.f); a1 = fmaxf(a1, 0.f);
        float s = a0*a0 + a1*a1;
        #pragma unroll
        for (int off = 16; off; off >>= 1) s += __shfl_xor_sync(0xffffffffu, s, off);
        float rn = rsqrtf(s);
        ((float2*)g_h)[node*32 + lane] = make_float2(a0*rn, a1*rn);
    }
}

// ---- launch 2: direct bucket CSR fill ----
__global__ void k_fill2(const void* __restrict__ ei) {
    int e = blockIdx.x*256 + threadIdx.x;
    int src, dst;
    if (g_is64) {
        const long long* p = (const long long*)ei;
        src = (int)p[e]; dst = (int)p[EE + e];
    } else {
        const int* p = (const int*)ei;
        src = p[e]; dst = p[EE + e];
    }
    int pos = atomicAdd(&g_deg[dst], 1);
    g_srcl[dst*CAP + pos] = src;
}

// ---- launches 3-5: gather + update, 4 nodes/warp, 512 thr, k-pair f32x2 GEMM ----
__global__ void __launch_bounds__(512, 2)
k_gup(const float* __restrict__ hin, float* __restrict__ hout) {
    extern __shared__ __align__(16) float4 dynsm[];
    float4* sWA = dynsm;          // 1024 float4 = 16KB : A[kp][o-pair packed]
    float4* sWB = dynsm + 1024;   // 1024 float4 = 16KB
    float4* sX  = dynsm + 2048;   // 16 warps * 4 nodes * 32 kp = 2048 float4 = 32KB
    int tid = threadIdx.x;
    for (int e = tid; e < 2048; e += 512) {
        sWA[e] = ((const float4*)g_AB)[e];          // first 1024: A, next 1024: B
    }
    __syncthreads();
    int lane = tid & 31, warp = tid >> 5;
    float4* myX = sX + warp*128;
    ull cinit0 = pk2(g_c[lane], 0.f);
    ull cinit1 = pk2(g_c[32 + lane], 0.f);
    int nb = (blockIdx.x*16 + warp)*4;

    // ---- gather phase: prefetch degs + first index vectors for all 4 nodes ----
    int deg[4], idx[4];
    #pragma unroll
    for (int t = 0; t < 4; ++t) deg[t] = g_deg[nb + t];
    #pragma unroll
    for (int t = 0; t < 4; ++t) {
        int n = deg[t] < 32 ? deg[t] : 32;
        idx[t] = (lane < n) ? g_srcl[(nb + t)*CAP + lane] : NN;
    }
    float2 macc[4];
    #pragma unroll
    for (int t = 0; t < 4; ++t) {
        int n = deg[t] < 32 ? deg[t] : 32;
        float2 m = make_float2(0.f, 0.f);
        int nr = (n + 7) & ~7;
        #pragma unroll 8
        for (int j = 0; j < nr; ++j) {
            int s = __shfl_sync(0xffffffffu, idx[t], j);
            float2 v = ((const float2*)hin)[s*32 + lane];
            m.x += v.x; m.y += v.y;
        }
        // rare tail (deg > 32)
        for (int b = 32; b < deg[t]; b += 32) {
            int nn = deg[t] - b; if (nn > 32) nn = 32;
            int id2 = (lane < nn) ? g_srcl[(nb + t)*CAP + b + lane] : NN;
            for (int j = 0; j < nn; ++j) {
                int s = __shfl_sync(0xffffffffu, id2, j);
                float2 v = ((const float2*)hin)[s*32 + lane];
                m.x += v.x; m.y += v.y;
            }
        }
        macc[t] = m;
    }
    #pragma unroll
    for (int t = 0; t < 4; ++t) {
        float2 h = ((const float2*)hin)[(nb + t)*32 + lane];
        myX[t*32 + lane] = make_float4(macc[t].x, macc[t].y, h.x, h.y);  // (m-pair, h-pair) for kp=lane
    }
    __syncwarp();

    // ---- GEMM phase: acc over k-pairs; outputs o=lane, o=lane+32 ----
    ull acc0[4], acc1[4];
    #pragma unroll
    for (int t = 0; t < 4; ++t) { acc0[t] = cinit0; acc1[t] = cinit1; }
    const ulonglong2* wa = (const ulonglong2*)sWA;
    const ulonglong2* wb = (const ulonglong2*)sWB;
    const ulonglong2* xp = (const ulonglong2*)myX;
    #pragma unroll 8
    for (int kp = 0; kp < 32; ++kp) {
        ulonglong2 A = wa[kp*32 + lane];   // .x: (A[o][2kp],A[o][2kp+1])  .y: o+32
        ulonglong2 B = wb[kp*32 + lane];
        #pragma unroll
        for (int t = 0; t < 4; ++t) {
            ulonglong2 xv = xp[t*32 + kp]; // broadcast: .x = m-pair, .y = h-pair
            acc0[t] = ff2(A.x, xv.x, acc0[t]);
            acc0[t] = ff2(B.x, xv.y, acc0[t]);
            acc1[t] = ff2(A.y, xv.x, acc1[t]);
            acc1[t] = ff2(B.y, xv.y, acc1[t]);
        }
    }
    // ---- epilogue ----
    float alo[4], ahi[4], s[4];
    #pragma unroll
    for (int t = 0; t < 4; ++t) {
        float2 p0 = up2(acc0[t]), p1 = up2(acc1[t]);
        alo[t] = fmaxf(p0.x + p0.y, 0.f);
        ahi[t] = fmaxf(p1.x + p1.y, 0.f);
        s[t] = alo[t]*alo[t] + ahi[t]*ahi[t];
    }
    #pragma unroll
    for (int off = 16; off; off >>= 1) {
        #pragma unroll
        for (int t = 0; t < 4; ++t) s[t] += __shfl_xor_sync(0xffffffffu, s[t], off);
    }
    #pragma unroll
    for (int t = 0; t < 4; ++t) {
        float rn = rsqrtf(s[t]);
        hout[(nb + t)*64 + lane]      = alo[t]*rn;
        hout[(nb + t)*64 + 32 + lane] = ahi[t]*rn;
    }
}

// ---- launch 6: Ag, 256 blocks (o x graph-chunk), 4 graphs/warp/pass; also zero g_deg ----
__global__ void k_ag(const float* __restrict__ W5, const float* __restrict__ hfin) {
    __shared__ __align__(16) float sWT[4096];     // [j][i]
    __shared__ __align__(16) float2 sL[8][4][64];
    int bi = blockIdx.x, tid = threadIdx.x;
    int o = bi >> 2, gc = bi & 3;
    if (tid < 128) g_deg[bi*128 + tid] = 0;       // reset cursors for next replay
    for (int e = tid; e < 4096; e += 256) {
        int i = e >> 6, j = e & 63;
        sWT[j*64 + i] = W5[o*4096 + e];
    }
    __syncthreads();
    int lane = tid & 31, warp = tid >> 5;
    const ull* wp = (const ull*)sWT;
    for (int pass = 0; pass < 2; ++pass) {
        int gbase = gc*64 + pass*32 + warp*4;
        #pragma unroll
        for (int t = 0; t < 4; ++t) {
            int g = gbase + t;
            float2 v = ((const float2*)hfin)[(g*128 + 127)*32 + lane];
            sL[warp][t][2*lane]     = make_float2(v.x, v.x);
            sL[warp][t][2*lane + 1] = make_float2(v.y, v.y);
        }
        __syncwarp();
        ull acc[4] = {0ULL, 0ULL, 0ULL, 0ULL};
        #pragma unroll 2
        for (int j = 0; j < 64; ++j) {
            ull w = wp[j*32 + lane];
            #pragma unroll
            for (int t = 0; t < 4; ++t) {
                ull xv = *(const ull*)&sL[warp][t][j];
                acc[t] = ff2(w, xv, acc[t]);
            }
        }
        __syncwarp();
        #pragma unroll
        for (int t = 0; t < 4; ++t) {
            int g = gbase + t;
            ((float2*)(g_Ag + g*4096 + o*64))[lane] = up2(acc[t]);
        }
    }
}

// ---- launch 7: fused y1 + head, 4 rows/warp/pass ----
__global__ void k_y1h(const float* __restrict__ hfin, const float* __restrict__ b5,
                      const float* __restrict__ Wd1, const float* __restrict__ bd1,
                      const float* __restrict__ Wd2, const float* __restrict__ bd2,
                      float* __restrict__ out) {
    extern __shared__ __align__(16) float dyn[];
    float*  sAgT = dyn;                   // 4096 [i][o]
    float*  sW1T = dyn + 4096;            // 8192 [k][j]
    float2* sY   = (float2*)(dyn + 4096 + 8192);  // 8*4*64 float2
    float*  sb5  = dyn + 4096 + 8192 + 4096;
    float*  sb1  = sb5 + 64;
    float*  sW2  = sb1 + 128;
    int g = blockIdx.x, tid = threadIdx.x;
    for (int e = tid; e < 4096; e += 256) {
        int o = e & 63, i = e >> 6;
        sAgT[i*64 + o] = g_Ag[g*4096 + o*64 + i];
    }
    for (int e = tid; e < 8192; e += 256) {
        int j = e >> 6, k = e & 63;
        sW1T[k*128 + j] = Wd1[e];
    }
    if (tid < 64) sb5[tid] = b5[tid];
    if (tid < 128) { sb1[tid] = bd1[tid]; sW2[tid] = Wd2[tid]; }
    __syncthreads();
    float bias2 = bd2[0];
    int lane = tid & 31, warp = tid >> 5;
    float2 (*sy)[64] = (float2 (*)[64])(sY + warp*256);
    const ull* ap = (const ull*)sAgT;
    const ulonglong2* wp = (const ulonglong2*)sW1T;
    const ull* b5p = (const ull*)sb5;
    for (int pass = 0; pass < 4; ++pass) {
        int rbase = pass*32 + warp*4;
        #pragma unroll
        for (int t = 0; t < 4; ++t) {
            int r = rbase + t;
            float2 v = (r < 127) ? ((const float2*)hfin)[(g*128 + r)*32 + lane]
                                 : make_float2(0.f, 0.f);
            sy[t][2*lane]     = make_float2(v.x, v.x);
            sy[t][2*lane + 1] = make_float2(v.y, v.y);
        }
        __syncwarp();
        ull ya[4];
        #pragma unroll
        for (int t = 0; t < 4; ++t) ya[t] = b5p[lane];
        #pragma unroll 2
        for (int i = 0; i < 64; ++i) {
            ull a = ap[i*32 + lane];
            #pragma unroll
            for (int t = 0; t < 4; ++t) {
                ull xv = *(const ull*)&sy[t][i];
                ya[t] = ff2(a, xv, ya[t]);
            }
        }
        __syncwarp();
        #pragma unroll
        for (int t = 0; t < 4; ++t) {
            float2 y = up2(ya[t]);
            sy[t][2*lane]     = make_float2(y.x, y.x);
            sy[t][2*lane + 1] = make_float2(y.y, y.y);
        }
        __syncwarp();
        ull z01[4], z23[4];
        #pragma unroll
        for (int t = 0; t < 4; ++t) {
            z01[t] = pk2(sb1[4*lane], sb1[4*lane + 1]);
            z23[t] = pk2(sb1[4*lane + 2], sb1[4*lane + 3]);
        }
        #pragma unroll 2
        for (int k = 0; k < 64; ++k) {
            ulonglong2 wv = wp[k*32 + lane];
            #pragma unroll
            for (int t = 0; t < 4; ++t) {
                ull yy = *(const ull*)&sy[t][k];
                z01[t] = ff2(wv.x, yy, z01[t]);
                z23[t] = ff2(wv.y, yy, z23[t]);
            }
        }
        __syncwarp();
        float4 w2 = *(float4*)&sW2[4*lane];
        #pragma unroll
        for (int t = 0; t < 4; ++t) {
            float2 za = up2(z01[t]), zb = up2(z23[t]);
            float acc = fmaxf(za.x, 0.f)*w2.x + fmaxf(za.y, 0.f)*w2.y +
                        fmaxf(zb.x, 0.f)*w2.z + fmaxf(zb.y, 0.f)*w2.w;
            #pragma unroll
            for (int off = 16; off; off >>= 1)
                acc += __shfl_xor_sync(0xffffffffu, acc, off);
            int r = rbase + t;
            if (lane == 0 && r < 127) out[g*127 + r] = acc + bias2;
        }
    }
}

extern "C" void kernel_launch(void* const* d_in, const int* in_sizes, int n_in,
                              void* d_out, int out_size) {
    const float* x = (const float*)d_in[0];
    const void*  ei = d_in[1];
    int base = (in_sizes[3] == 1) ? 4 : 3;
    const float* W1  = (const float*)d_in[base + 0];
    const float* b1  = (const float*)d_in[base + 1];
    const float* W2  = (const float*)d_in[base + 2];
    const float* b2  = (const float*)d_in[base + 3];
    const float* W3  = (const float*)d_in[base + 4];
    const float* b3  = (const float*)d_in[base + 5];
    const float* W4  = (const float*)d_in[base + 6];
    const float* b4  = (const float*)d_in[base + 7];
    const float* W5  = (const float*)d_in[base + 8];
    const float* b5  = (const float*)d_in[base + 9];
    const float* Wd1 = (const float*)d_in[base + 10];
    const float* bd1 = (const float*)d_in[base + 11];
    const float* Wd2 = (const float*)d_in[base + 12];
    const float* bd2 = (const float*)d_in[base + 13];
    float* out = (float*)d_out;

    float *hA = nullptr, *hB = nullptr;
    cudaGetSymbolAddress((void**)&hA, g_h);
    cudaGetSymbolAddress((void**)&hB, g_m);

    // idempotent; no static host state
    cudaFuncSetAttribute(k_gup, cudaFuncAttributeMaxDynamicSharedMemorySize, 72*1024);
    cudaFuncSetAttribute(k_y1h, cudaFuncAttributeMaxDynamicSharedMemorySize, 72*1024);
    int gup_smem = 4096 * 16;                                 // 64KB
    int y1h_smem = (4096 + 8192 + 4096 + 64 + 128 + 128) * 4; // ~66KB

    k_pi<<<529, 256>>>(x, ei, W1, b1, W2, b2, W3, b3, W4, b4);    // launch 1
    k_fill2<<<EE/256, 256>>>(ei);                                  // launch 2
    k_gup<<<NN/64, 512, gup_smem>>>(hA, hB);                       // launch 3
    k_gup<<<NN/64, 512, gup_smem>>>(hB, hA);                       // launch 4 <- ncu capture
    k_gup<<<NN/64, 512, gup_smem>>>(hA, hB);                       // launch 5
    k_ag<<<256, 256>>>(W5, hB);                                    // launch 6
    k_y1h<<<GG, 256, y1h_smem>>>(hB, b5, Wd1, bd1, Wd2, bd2, out); // launch 7
}

// round 10
// speedup vs baseline: 1.7995x; 1.0132x over previous
#include <cuda_runtime.h>

#define NN 32768
#define GG 256
#define PP 128
#define EE 524288
#define HH 64
#define CAP 96
#define ROWS (GG*(PP-1))

typedef unsigned long long ull;

// ---- device scratch ----
__device__ __align__(16) float g_h[(NN+1)*HH];   // +1 sentinel zero row
__device__ __align__(16) float g_m[(NN+1)*HH];
__device__ __align__(16) float g_Ag[GG*HH*HH];
__device__ __align__(16) float g_AB[HH*HH*2];    // A table [0,4096), B table [4096,8192), k-pair packed
__device__ __align__(16) float g_c[HH];
__device__ int   g_is64;
__device__ __align__(16) int g_deg[NN];          // zeroed at end of k_ag each replay
__device__ int g_srcl[NN*CAP];

// ---- f32x2 helpers ----
__device__ __forceinline__ ull pk2(float x, float y) {
    ull r; asm("mov.b64 %0,{%1,%2};" : "=l"(r) : "f"(x), "f"(y)); return r;
}
__device__ __forceinline__ ull ff2(ull a, ull b, ull c) {
    ull d; asm("fma.rn.f32x2 %0,%1,%2,%3;" : "=l"(d) : "l"(a), "l"(b), "l"(c)); return d;
}
__device__ __forceinline__ ull ad2(ull a, ull b) {
    ull d; asm("add.rn.f32x2 %0,%1,%2;" : "=l"(d) : "l"(a), "l"(b)); return d;
}
__device__ __forceinline__ float2 up2(ull a) {
    float x, y; asm("mov.b64 {%0,%1},%2;" : "=f"(x), "=f"(y) : "l"(a));
    return make_float2(x, y);
}

// ---- launch 1: weights (blk 0-15), bias+detect+sentinel (blk 16), input layer (17+) ----
__global__ void k_pi(const float* __restrict__ x, const void* __restrict__ ei,
                     const float* __restrict__ W1, const float* __restrict__ b1,
                     const float* __restrict__ W2, const float* __restrict__ b2,
                     const float* __restrict__ W3, const float* __restrict__ b3,
                     const float* __restrict__ W4, const float* __restrict__ b4) {
    int tid = threadIdx.x;
    if (blockIdx.x < 16) {
        int e = blockIdx.x * 256 + tid;
        int o = e >> 6, k = e & 63;
        float a = 0.f, b = 0.f;
        for (int t = 0; t < 64; ++t) {
            a += W4[o*128 + t]      * W3[t*64 + k];
            b += W4[o*128 + 64 + t] * W2[t*64 + k];
        }
        // k-pair packed: float4 at (kp*32 + (o&31)) holds {X[o][2kp],X[o][2kp+1],X[o+32][2kp],X[o+32][2kp+1]}
        int kp = k >> 1, ob = o & 31, comp = ((o >> 5) << 1) | (k & 1);
        g_AB[(kp*32 + ob)*4 + comp]        = a;
        g_AB[4096 + (kp*32 + ob)*4 + comp] = b;
        return;
    }
    if (blockIdx.x == 16) {
        if (tid < 64) {
            float c = b4[tid];
            for (int t = 0; t < 64; ++t)
                c += W4[tid*128 + t]*b3[t] + W4[tid*128 + 64 + t]*b2[t];
            g_c[tid] = c;
            g_h[NN*64 + tid] = 0.f;   // sentinel rows
            g_m[NN*64 + tid] = 0.f;
        }
        const int* ei32 = (const int*)ei;
        int bad = 0;
        for (int i = tid; i < 2048; i += 256) bad |= (ei32[2*i + 1] != 0);
        int any = __syncthreads_or(bad);
        if (tid == 0) g_is64 = !any;
        return;
    }
    __shared__ __align__(16) float sW[8*64];
    __shared__ float sb[64];
    for (int e = tid; e < 512; e += 256) {
        int o = e >> 3, j = e & 7;
        sW[j*64 + o] = W1[e];
    }
    if (tid < 64) sb[tid] = b1[tid];
    __syncthreads();
    int lane = tid & 31, warp = tid >> 5;
    for (int node = (blockIdx.x - 17)*8 + warp; node < NN; node += 512*8) {
        float xv = (lane < 8) ? x[node*8 + lane] : 0.f;
        float a0 = sb[2*lane], a1 = sb[2*lane + 1];
        #pragma unroll
        for (int j = 0; j < 8; ++j) {
            float xj = __shfl_sync(0xffffffffu, xv, j);
            a0 += sW[j*64 + 2*lane]     * xj;
            a1 += sW[j*64 + 2*lane + 1] * xj;
        }
        a0 = fmaxf(a0, 0.f); a1 = fmaxf(a1, 0.f);
        float s = a0*a0 + a1*a1;
        #pragma unroll
        for (int off = 16; off; off >>= 1) s += __shfl_xor_sync(0xffffffffu, s, off);
        float rn = rsqrtf(s);
        ((float2*)g_h)[node*32 + lane] = make_float2(a0*rn, a1*rn);
    }
}

// ---- launch 2: direct bucket CSR fill, 2 edges/thread ----
__global__ void k_fill2(const void* __restrict__ ei) {
    int e = (blockIdx.x*256 + threadIdx.x)*2;
    int s0, s1, d0, d1;
    if (g_is64) {
        const longlong2* ps = (const longlong2*)((const long long*)ei + e);
        const longlong2* pd = (const longlong2*)((const long long*)ei + EE + e);
        longlong2 sv = *ps, dv = *pd;
        s0 = (int)sv.x; s1 = (int)sv.y; d0 = (int)dv.x; d1 = (int)dv.y;
    } else {
        const int2* ps = (const int2*)((const int*)ei + e);
        const int2* pd = (const int2*)((const int*)ei + EE + e);
        int2 sv = *ps, dv = *pd;
        s0 = sv.x; s1 = sv.y; d0 = dv.x; d1 = dv.y;
    }
    int p0 = atomicAdd(&g_deg[d0], 1);
    g_srcl[d0*CAP + p0] = s0;
    int p1 = atomicAdd(&g_deg[d1], 1);
    g_srcl[d1*CAP + p1] = s1;
}

// ---- launches 3-5: gather + update, 4 nodes/warp, 512 thr, k-pair f32x2 GEMM ----
__global__ void __launch_bounds__(512, 2)
k_gup(const float* __restrict__ hin, float* __restrict__ hout) {
    extern __shared__ __align__(16) float4 dynsm[];
    float4* sWA = dynsm;          // 1024 float4 = 16KB : A[kp][o-pair packed]
    float4* sWB = dynsm + 1024;   // 1024 float4 = 16KB
    ulonglong2* sX = (ulonglong2*)(dynsm + 2048);  // 16 warps * 4 nodes * 32 kp = 32KB
    int tid = threadIdx.x;
    for (int e = tid; e < 2048; e += 512) {
        sWA[e] = ((const float4*)g_AB)[e];          // first 1024: A, next 1024: B
    }
    __syncthreads();
    int lane = tid & 31, warp = tid >> 5;
    ulonglong2* myX = sX + warp*128;
    ull cinit0 = pk2(g_c[lane], 0.f);
    ull cinit1 = pk2(g_c[32 + lane], 0.f);
    int nb = (blockIdx.x*16 + warp)*4;
    const ull* hin64 = (const ull*)hin;

    // ---- gather phase: prefetch degs + first index vectors for all 4 nodes ----
    int deg[4], idx[4];
    #pragma unroll
    for (int t = 0; t < 4; ++t) deg[t] = g_deg[nb + t];
    #pragma unroll
    for (int t = 0; t < 4; ++t) {
        int n = deg[t] < 32 ? deg[t] : 32;
        idx[t] = (lane < n) ? g_srcl[(nb + t)*CAP + lane] : NN;
    }
    #pragma unroll
    for (int t = 0; t < 4; ++t) {
        int n = deg[t] < 32 ? deg[t] : 32;
        ull m0 = 0ULL, m1 = 0ULL;   // f32x2 accumulators (0.0f bits)
        int nr = (n + 7) & ~7;
        #pragma unroll 8
        for (int j = 0; j < nr; j += 2) {
            int sa = __shfl_sync(0xffffffffu, idx[t], j);
            int sb = __shfl_sync(0xffffffffu, idx[t], j + 1);
            m0 = ad2(m0, hin64[sa*32 + lane]);
            m1 = ad2(m1, hin64[sb*32 + lane]);
        }
        // rare tail (deg > 32)
        for (int b = 32; b < deg[t]; b += 32) {
            int nn = deg[t] - b; if (nn > 32) nn = 32;
            int id2 = (lane < nn) ? g_srcl[(nb + t)*CAP + b + lane] : NN;
            for (int j = 0; j < nn; ++j) {
                int s = __shfl_sync(0xffffffffu, id2, j);
                m0 = ad2(m0, hin64[s*32 + lane]);
            }
        }
        ull mv = ad2(m0, m1);
        ull hv = hin64[(nb + t)*32 + lane];
        myX[t*32 + lane] = make_ulonglong2(mv, hv);   // (m-pair, h-pair) for kp=lane
    }
    __syncwarp();

    // ---- GEMM phase: acc over k-pairs; outputs o=lane, o=lane+32 ----
    ull acc0[4], acc1[4];
    #pragma unroll
    for (int t = 0; t < 4; ++t) { acc0[t] = cinit0; acc1[t] = cinit1; }
    const ulonglong2* wa = (const ulonglong2*)sWA;
    const ulonglong2* wb = (const ulonglong2*)sWB;
    #pragma unroll
    for (int kp = 0; kp < 32; ++kp) {
        ulonglong2 A = wa[kp*32 + lane];   // .x: (A[o][2kp],A[o][2kp+1])  .y: o+32
        ulonglong2 B = wb[kp*32 + lane];
        #pragma unroll
        for (int t = 0; t < 4; ++t) {
            ulonglong2 xv = myX[t*32 + kp]; // broadcast: .x = m-pair, .y = h-pair
            acc0[t] = ff2(A.x, xv.x, acc0[t]);
            acc0[t] = ff2(B.x, xv.y, acc0[t]);
            acc1[t] = ff2(A.y, xv.x, acc1[t]);
            acc1[t] = ff2(B.y, xv.y, acc1[t]);
        }
    }
    // ---- epilogue ----
    float alo[4], ahi[4], s[4];
    #pragma unroll
    for (int t = 0; t < 4; ++t) {
        float2 p0 = up2(acc0[t]), p1 = up2(acc1[t]);
        alo[t] = fmaxf(p0.x + p0.y, 0.f);
        ahi[t] = fmaxf(p1.x + p1.y, 0.f);
        s[t] = alo[t]*alo[t] + ahi[t]*ahi[t];
    }
    #pragma unroll
    for (int off = 16; off; off >>= 1) {
        #pragma unroll
        for (int t = 0; t < 4; ++t) s[t] += __shfl_xor_sync(0xffffffffu, s[t], off);
    }
    #pragma unroll
    for (int t = 0; t < 4; ++t) {
        float rn = rsqrtf(s[t]);
        hout[(nb + t)*64 + lane]      = alo[t]*rn;
        hout[(nb + t)*64 + 32 + lane] = ahi[t]*rn;
    }
}

// ---- launch 6: Ag, 256 blocks (o x graph-chunk), 4 graphs/warp/pass; also zero g_deg ----
__global__ void k_ag(const float* __restrict__ W5, const float* __restrict__ hfin) {
    __shared__ __align__(16) float sWT[4096];     // [j][i]
    __shared__ __align__(16) float2 sL[8][4][64];
    int bi = blockIdx.x, tid = threadIdx.x;
    int o = bi >> 2, gc = bi & 3;
    if (tid < 128) g_deg[bi*128 + tid] = 0;       // reset cursors for next replay
    for (int e = tid; e < 4096; e += 256) {
        int i = e >> 6, j = e & 63;
        sWT[j*64 + i] = W5[o*4096 + e];
    }
    __syncthreads();
    int lane = tid & 31, warp = tid >> 5;
    const ull* wp = (const ull*)sWT;
    for (int pass = 0; pass < 2; ++pass) {
        int gbase = gc*64 + pass*32 + warp*4;
        #pragma unroll
        for (int t = 0; t < 4; ++t) {
            int g = gbase + t;
            float2 v = ((const float2*)hfin)[(g*128 + 127)*32 + lane];
            sL[warp][t][2*lane]     = make_float2(v.x, v.x);
            sL[warp][t][2*lane + 1] = make_float2(v.y, v.y);
        }
        __syncwarp();
        ull acc[4] = {0ULL, 0ULL, 0ULL, 0ULL};
        #pragma unroll 2
        for (int j = 0; j < 64; ++j) {
            ull w = wp[j*32 + lane];
            #pragma unroll
            for (int t = 0; t < 4; ++t) {
                ull xv = *(const ull*)&sL[warp][t][j];
                acc[t] = ff2(w, xv, acc[t]);
            }
        }
        __syncwarp();
        #pragma unroll
        for (int t = 0; t < 4; ++t) {
            int g = gbase + t;
            ((float2*)(g_Ag + g*4096 + o*64))[lane] = up2(acc[t]);
        }
    }
}

// ---- launch 7: fused y1 + head, 4 rows/warp/pass ----
__global__ void k_y1h(const float* __restrict__ hfin, const float* __restrict__ b5,
                      const float* __restrict__ Wd1, const float* __restrict__ bd1,
                      const float* __restrict__ Wd2, const float* __restrict__ bd2,
                      float* __restrict__ out) {
    extern __shared__ __align__(16) float dyn[];
    float*  sAgT = dyn;                   // 4096 [i][o]
    float*  sW1T = dyn + 4096;            // 8192 [k][j]
    float2* sY   = (float2*)(dyn + 4096 + 8192);  // 8*4*64 float2
    float*  sb5  = dyn + 4096 + 8192 + 4096;
    float*  sb1  = sb5 + 64;
    float*  sW2  = sb1 + 128;
    int g = blockIdx.x, tid = threadIdx.x;
    for (int e = tid; e < 4096; e += 256) {
        int o = e & 63, i = e >> 6;
        sAgT[i*64 + o] = g_Ag[g*4096 + o*64 + i];
    }
    for (int e = tid; e < 8192; e += 256) {
        int j = e >> 6, k = e & 63;
        sW1T[k*128 + j] = Wd1[e];
    }
    if (tid < 64) sb5[tid] = b5[tid];
    if (tid < 128) { sb1[tid] = bd1[tid]; sW2[tid] = Wd2[tid]; }
    __syncthreads();
    float bias2 = bd2[0];
    int lane = tid & 31, warp = tid >> 5;
    float2 (*sy)[64] = (float2 (*)[64])(sY + warp*256);
    const ull* ap = (const ull*)sAgT;
    const ulonglong2* wp = (const ulonglong2*)sW1T;
    const ull* b5p = (const ull*)sb5;
    for (int pass = 0; pass < 4; ++pass) {
        int rbase = pass*32 + warp*4;
        #pragma unroll
        for (int t = 0; t < 4; ++t) {
            int r = rbase + t;
            float2 v = (r < 127) ? ((const float2*)hfin)[(g*128 + r)*32 + lane]
                                 : make_float2(0.f, 0.f);
            sy[t][2*lane]     = make_float2(v.x, v.x);
            sy[t][2*lane + 1] = make_float2(v.y, v.y);
        }
        __syncwarp();
        ull ya[4];
        #pragma unroll
        for (int t = 0; t < 4; ++t) ya[t] = b5p[lane];
        #pragma unroll 2
        for (int i = 0; i < 64; ++i) {
            ull a = ap[i*32 + lane];
            #pragma unroll
            for (int t = 0; t < 4; ++t) {
                ull xv = *(const ull*)&sy[t][i];
                ya[t] = ff2(a, xv, ya[t]);
            }
        }
        __syncwarp();
        #pragma unroll
        for (int t = 0; t < 4; ++t) {
            float2 y = up2(ya[t]);
            sy[t][2*lane]     = make_float2(y.x, y.x);
            sy[t][2*lane + 1] = make_float2(y.y, y.y);
        }
        __syncwarp();
        ull z01[4], z23[4];
        #pragma unroll
        for (int t = 0; t < 4; ++t) {
            z01[t] = pk2(sb1[4*lane], sb1[4*lane + 1]);
            z23[t] = pk2(sb1[4*lane + 2], sb1[4*lane + 3]);
        }
        #pragma unroll 2
        for (int k = 0; k < 64; ++k) {
            ulonglong2 wv = wp[k*32 + lane];
            #pragma unroll
            for (int t = 0; t < 4; ++t) {
                ull yy = *(const ull*)&sy[t][k];
                z01[t] = ff2(wv.x, yy, z01[t]);
                z23[t] = ff2(wv.y, yy, z23[t]);
            }
        }
        __syncwarp();
        float4 w2 = *(float4*)&sW2[4*lane];
        #pragma unroll
        for (int t = 0; t < 4; ++t) {
            float2 za = up2(z01[t]), zb = up2(z23[t]);
            float acc = fmaxf(za.x, 0.f)*w2.x + fmaxf(za.y, 0.f)*w2.y +
                        fmaxf(zb.x, 0.f)*w2.z + fmaxf(zb.y, 0.f)*w2.w;
            #pragma unroll
            for (int off = 16; off; off >>= 1)
                acc += __shfl_xor_sync(0xffffffffu, acc, off);
            int r = rbase + t;
            if (lane == 0 && r < 127) out[g*127 + r] = acc + bias2;
        }
    }
}

extern "C" void kernel_launch(void* const* d_in, const int* in_sizes, int n_in,
                              void* d_out, int out_size) {
    const float* x = (const float*)d_in[0];
    const void*  ei = d_in[1];
    int base = (in_sizes[3] == 1) ? 4 : 3;
    const float* W1  = (const float*)d_in[base + 0];
    const float* b1  = (const float*)d_in[base + 1];
    const float* W2  = (const float*)d_in[base + 2];
    const float* b2  = (const float*)d_in[base + 3];
    const float* W3  = (const float*)d_in[base + 4];
    const float* b3  = (const float*)d_in[base + 5];
    const float* W4  = (const float*)d_in[base + 6];
    const float* b4  = (const float*)d_in[base + 7];
    const float* W5  = (const float*)d_in[base + 8];
    const float* b5  = (const float*)d_in[base + 9];
    const float* Wd1 = (const float*)d_in[base + 10];
    const float* bd1 = (const float*)d_in[base + 11];
    const float* Wd2 = (const float*)d_in[base + 12];
    const float* bd2 = (const float*)d_in[base + 13];
    float* out = (float*)d_out;

    float *hA = nullptr, *hB = nullptr;
    cudaGetSymbolAddress((void**)&hA, g_h);
    cudaGetSymbolAddress((void**)&hB, g_m);

    cudaFuncSetAttribute(k_gup, cudaFuncAttributeMaxDynamicSharedMemorySize, 72*1024);
    cudaFuncSetAttribute(k_y1h, cudaFuncAttributeMaxDynamicSharedMemorySize, 72*1024);
    int gup_smem = 4096 * 16;                                 // 64KB
    int y1h_smem = (4096 + 8192 + 4096 + 64 + 128 + 128) * 4; // ~66KB

    k_pi<<<529, 256>>>(x, ei, W1, b1, W2, b2, W3, b3, W4, b4);    // launch 1
    k_fill2<<<EE/512, 256>>>(ei);                                  // launch 2
    k_gup<<<NN/64, 512, gup_smem>>>(hA, hB);                       // launch 3
    k_gup<<<NN/64, 512, gup_smem>>>(hB, hA);                       // launch 4 <- ncu capture
    k_gup<<<NN/64, 512, gup_smem>>>(hA, hB);                       // launch 5
    k_ag<<<256, 256>>>(W5, hB);                                    // launch 6
    k_y1h<<<GG, 256, y1h_smem>>>(hB, b5, Wd1, bd1, Wd2, bd2, out); // launch 7
}

// round 11
// speedup vs baseline: 1.8482x; 1.0271x over previous
#include <cuda_runtime.h>

#define NN 32768
#define GG 256
#define PP 128
#define EE 524288
#define HH 64
#define CAP 96
#define ROWS (GG*(PP-1))

typedef unsigned long long ull;

// ---- device scratch ----
__device__ __align__(16) float g_h[(NN+1)*HH];   // +1 sentinel zero row
__device__ __align__(16) float g_m[(NN+1)*HH];
__device__ __align__(16) float g_Ag[GG*HH*HH];
__device__ __align__(16) float g_AB[HH*HH*2];    // A table [0,4096), B table [4096,8192), k-pair packed
__device__ __align__(16) float g_c[HH];
__device__ __align__(16) int g_deg[NN];          // zeroed at end of k_ag each replay
__device__ int g_srcl[NN*CAP];

// ---- f32x2 helpers ----
__device__ __forceinline__ ull pk2(float x, float y) {
    ull r; asm("mov.b64 %0,{%1,%2};" : "=l"(r) : "f"(x), "f"(y)); return r;
}
__device__ __forceinline__ ull ff2(ull a, ull b, ull c) {
    ull d; asm("fma.rn.f32x2 %0,%1,%2,%3;" : "=l"(d) : "l"(a), "l"(b), "l"(c)); return d;
}
__device__ __forceinline__ ull ad2(ull a, ull b) {
    ull d; asm("add.rn.f32x2 %0,%1,%2;" : "=l"(d) : "l"(a), "l"(b)); return d;
}
__device__ __forceinline__ float2 up2(ull a) {
    float x, y; asm("mov.b64 {%0,%1},%2;" : "=f"(x), "=f"(y) : "l"(a));
    return make_float2(x, y);
}

// ---- launch 1: weights (blk 0-15), bias+sentinel (blk 16), input layer (17-528),
//                CSR bucket fill (blk 529-1552, overlapped) ----
__global__ void k_pi(const float* __restrict__ x, const void* __restrict__ ei,
                     const float* __restrict__ W1, const float* __restrict__ b1,
                     const float* __restrict__ W2, const float* __restrict__ b2,
                     const float* __restrict__ W3, const float* __restrict__ b3,
                     const float* __restrict__ W4, const float* __restrict__ b4) {
    int tid = threadIdx.x;
    if (blockIdx.x >= 529) {
        // ---- CSR fill, 2 edges/thread; local int64 detection (256 high-words) ----
        const int* ei32 = (const int*)ei;
        int bad = (ei32[2*tid + 1] != 0);
        int is64 = !__syncthreads_or(bad);
        int e = ((int)(blockIdx.x - 529)*256 + tid)*2;
        int s0, s1, d0, d1;
        if (is64) {
            longlong2 sv = *(const longlong2*)((const long long*)ei + e);
            longlong2 dv = *(const longlong2*)((const long long*)ei + EE + e);
            s0 = (int)sv.x; s1 = (int)sv.y; d0 = (int)dv.x; d1 = (int)dv.y;
        } else {
            int2 sv = *(const int2*)(ei32 + e);
            int2 dv = *(const int2*)(ei32 + EE + e);
            s0 = sv.x; s1 = sv.y; d0 = dv.x; d1 = dv.y;
        }
        int p0 = atomicAdd(&g_deg[d0], 1);
        g_srcl[d0*CAP + p0] = s0;
        int p1 = atomicAdd(&g_deg[d1], 1);
        g_srcl[d1*CAP + p1] = s1;
        return;
    }
    if (blockIdx.x < 16) {
        int e = blockIdx.x * 256 + tid;
        int o = e >> 6, k = e & 63;
        float a = 0.f, b = 0.f;
        for (int t = 0; t < 64; ++t) {
            a += W4[o*128 + t]      * W3[t*64 + k];
            b += W4[o*128 + 64 + t] * W2[t*64 + k];
        }
        // k-pair packed: float4 at (kp*32 + (o&31)) = {X[o][2kp],X[o][2kp+1],X[o+32][2kp],X[o+32][2kp+1]}
        int kp = k >> 1, ob = o & 31, comp = ((o >> 5) << 1) | (k & 1);
        g_AB[(kp*32 + ob)*4 + comp]        = a;
        g_AB[4096 + (kp*32 + ob)*4 + comp] = b;
        return;
    }
    if (blockIdx.x == 16) {
        if (tid < 64) {
            float c = b4[tid];
            for (int t = 0; t < 64; ++t)
                c += W4[tid*128 + t]*b3[t] + W4[tid*128 + 64 + t]*b2[t];
            g_c[tid] = c;
            g_h[NN*64 + tid] = 0.f;   // sentinel rows
            g_m[NN*64 + tid] = 0.f;
        }
        return;
    }
    // ---- input layer ----
    __shared__ __align__(16) float sW[8*64];
    __shared__ float sb[64];
    for (int e = tid; e < 512; e += 256) {
        int o = e >> 3, j = e & 7;
        sW[j*64 + o] = W1[e];
    }
    if (tid < 64) sb[tid] = b1[tid];
    __syncthreads();
    int lane = tid & 31, warp = tid >> 5;
    for (int node = (blockIdx.x - 17)*8 + warp; node < NN; node += 512*8) {
        float xv = (lane < 8) ? x[node*8 + lane] : 0.f;
        float a0 = sb[2*lane], a1 = sb[2*lane + 1];
        #pragma unroll
        for (int j = 0; j < 8; ++j) {
            float xj = __shfl_sync(0xffffffffu, xv, j);
            a0 += sW[j*64 + 2*lane]     * xj;
            a1 += sW[j*64 + 2*lane + 1] * xj;
        }
        a0 = fmaxf(a0, 0.f); a1 = fmaxf(a1, 0.f);
        float s = a0*a0 + a1*a1;
        #pragma unroll
        for (int off = 16; off; off >>= 1) s += __shfl_xor_sync(0xffffffffu, s, off);
        float rn = rsqrtf(s);
        ((float2*)g_h)[node*32 + lane] = make_float2(a0*rn, a1*rn);
    }
}

// ---- launches 2-4: gather + update; 8-warp blocks, 4 blocks/SM, warp-strided groups ----
__global__ void __launch_bounds__(256, 4)
k_gup(const float* __restrict__ hin, float* __restrict__ hout) {
    extern __shared__ __align__(16) float4 dynsm[];
    float4* sWA = dynsm;          // 1024 float4 = 16KB : A[kp][o-pair packed]
    float4* sWB = dynsm + 1024;   // 1024 float4 = 16KB
    ulonglong2* sX = (ulonglong2*)(dynsm + 2048);  // 8 warps * 4 nodes * 32 kp = 16KB
    int tid = threadIdx.x;
    for (int e = tid; e < 2048; e += 256) {
        sWA[e] = ((const float4*)g_AB)[e];          // first 1024: A, next 1024: B
    }
    __syncthreads();
    int lane = tid & 31, warp = tid >> 5;
    ulonglong2* myX = sX + warp*128;
    ull cinit0 = pk2(g_c[lane], 0.f);
    ull cinit1 = pk2(g_c[32 + lane], 0.f);
    const ull* hin64 = (const ull*)hin;
    const ulonglong2* wa = (const ulonglong2*)sWA;
    const ulonglong2* wb = (const ulonglong2*)sWB;

    for (int grp = blockIdx.x*8 + warp; grp < NN/4; grp += 4736) {
        int nb = grp*4;
        // ---- gather phase ----
        int deg[4], idx[4];
        #pragma unroll
        for (int t = 0; t < 4; ++t) deg[t] = g_deg[nb + t];
        #pragma unroll
        for (int t = 0; t < 4; ++t) {
            int n = deg[t] < 32 ? deg[t] : 32;
            idx[t] = (lane < n) ? g_srcl[(nb + t)*CAP + lane] : NN;
        }
        #pragma unroll
        for (int t = 0; t < 4; ++t) {
            int n = deg[t] < 32 ? deg[t] : 32;
            ull m0 = 0ULL, m1 = 0ULL;
            int nr = (n + 7) & ~7;
            #pragma unroll 8
            for (int j = 0; j < nr; j += 2) {
                int sa = __shfl_sync(0xffffffffu, idx[t], j);
                int sb = __shfl_sync(0xffffffffu, idx[t], j + 1);
                m0 = ad2(m0, hin64[sa*32 + lane]);
                m1 = ad2(m1, hin64[sb*32 + lane]);
            }
            for (int b = 32; b < deg[t]; b += 32) {   // rare tail
                int nn = deg[t] - b; if (nn > 32) nn = 32;
                int id2 = (lane < nn) ? g_srcl[(nb + t)*CAP + b + lane] : NN;
                for (int j = 0; j < nn; ++j) {
                    int s = __shfl_sync(0xffffffffu, id2, j);
                    m0 = ad2(m0, hin64[s*32 + lane]);
                }
            }
            ull mv = ad2(m0, m1);
            ull hv = hin64[(nb + t)*32 + lane];
            myX[t*32 + lane] = make_ulonglong2(mv, hv);
        }
        __syncwarp();
        // ---- GEMM phase ----
        ull acc0[4], acc1[4];
        #pragma unroll
        for (int t = 0; t < 4; ++t) { acc0[t] = cinit0; acc1[t] = cinit1; }
        #pragma unroll
        for (int kp = 0; kp < 32; ++kp) {
            ulonglong2 A = wa[kp*32 + lane];
            ulonglong2 B = wb[kp*32 + lane];
            #pragma unroll
            for (int t = 0; t < 4; ++t) {
                ulonglong2 xv = myX[t*32 + kp];
                acc0[t] = ff2(A.x, xv.x, acc0[t]);
                acc0[t] = ff2(B.x, xv.y, acc0[t]);
                acc1[t] = ff2(A.y, xv.x, acc1[t]);
                acc1[t] = ff2(B.y, xv.y, acc1[t]);
            }
        }
        // ---- epilogue ----
        float alo[4], ahi[4], s[4];
        #pragma unroll
        for (int t = 0; t < 4; ++t) {
            float2 p0 = up2(acc0[t]), p1 = up2(acc1[t]);
            alo[t] = fmaxf(p0.x + p0.y, 0.f);
            ahi[t] = fmaxf(p1.x + p1.y, 0.f);
            s[t] = alo[t]*alo[t] + ahi[t]*ahi[t];
        }
        #pragma unroll
        for (int off = 16; off; off >>= 1) {
            #pragma unroll
            for (int t = 0; t < 4; ++t) s[t] += __shfl_xor_sync(0xffffffffu, s[t], off);
        }
        #pragma unroll
        for (int t = 0; t < 4; ++t) {
            float rn = rsqrtf(s[t]);
            hout[(nb + t)*64 + lane]      = alo[t]*rn;
            hout[(nb + t)*64 + 32 + lane] = ahi[t]*rn;
        }
        __syncwarp();
    }
}

// ---- launch 5: Ag, 256 blocks (o x graph-chunk), 4 graphs/warp/pass; also zero g_deg ----
__global__ void k_ag(const float* __restrict__ W5, const float* __restrict__ hfin) {
    __shared__ __align__(16) float sWT[4096];     // [j][i]
    __shared__ __align__(16) float2 sL[8][4][64];
    int bi = blockIdx.x, tid = threadIdx.x;
    int o = bi >> 2, gc = bi & 3;
    if (tid < 128) g_deg[bi*128 + tid] = 0;       // reset cursors for next replay
    for (int e = tid; e < 4096; e += 256) {
        int i = e >> 6, j = e & 63;
        sWT[j*64 + i] = W5[o*4096 + e];
    }
    __syncthreads();
    int lane = tid & 31, warp = tid >> 5;
    const ull* wp = (const ull*)sWT;
    for (int pass = 0; pass < 2; ++pass) {
        int gbase = gc*64 + pass*32 + warp*4;
        #pragma unroll
        for (int t = 0; t < 4; ++t) {
            int g = gbase + t;
            float2 v = ((const float2*)hfin)[(g*128 + 127)*32 + lane];
            sL[warp][t][2*lane]     = make_float2(v.x, v.x);
            sL[warp][t][2*lane + 1] = make_float2(v.y, v.y);
        }
        __syncwarp();
        ull acc[4] = {0ULL, 0ULL, 0ULL, 0ULL};
        #pragma unroll 2
        for (int j = 0; j < 64; ++j) {
            ull w = wp[j*32 + lane];
            #pragma unroll
            for (int t = 0; t < 4; ++t) {
                ull xv = *(const ull*)&sL[warp][t][j];
                acc[t] = ff2(w, xv, acc[t]);
            }
        }
        __syncwarp();
        #pragma unroll
        for (int t = 0; t < 4; ++t) {
            int g = gbase + t;
            ((float2*)(g_Ag + g*4096 + o*64))[lane] = up2(acc[t]);
        }
    }
}

// ---- launch 6: fused y1 + head, 4 rows/warp/pass ----
__global__ void k_y1h(const float* __restrict__ hfin, const float* __restrict__ b5,
                      const float* __restrict__ Wd1, const float* __restrict__ bd1,
                      const float* __restrict__ Wd2, const float* __restrict__ bd2,
                      float* __restrict__ out) {
    extern __shared__ __align__(16) float dyn[];
    float*  sAgT = dyn;                   // 4096 [i][o]
    float*  sW1T = dyn + 4096;            // 8192 [k][j]
    float2* sY   = (float2*)(dyn + 4096 + 8192);  // 8*4*64 float2
    float*  sb5  = dyn + 4096 + 8192 + 4096;
    float*  sb1  = sb5 + 64;
    float*  sW2  = sb1 + 128;
    int g = blockIdx.x, tid = threadIdx.x;
    for (int e = tid; e < 4096; e += 256) {
        int o = e & 63, i = e >> 6;
        sAgT[i*64 + o] = g_Ag[g*4096 + o*64 + i];
    }
    for (int e = tid; e < 8192; e += 256) {
        int j = e >> 6, k = e & 63;
        sW1T[k*128 + j] = Wd1[e];
    }
    if (tid < 64) sb5[tid] = b5[tid];
    if (tid < 128) { sb1[tid] = bd1[tid]; sW2[tid] = Wd2[tid]; }
    __syncthreads();
    float bias2 = bd2[0];
    int lane = tid & 31, warp = tid >> 5;
    float2 (*sy)[64] = (float2 (*)[64])(sY + warp*256);
    const ull* ap = (const ull*)sAgT;
    const ulonglong2* wp = (const ulonglong2*)sW1T;
    const ull* b5p = (const ull*)sb5;
    for (int pass = 0; pass < 4; ++pass) {
        int rbase = pass*32 + warp*4;
        #pragma unroll
        for (int t = 0; t < 4; ++t) {
            int r = rbase + t;
            float2 v = (r < 127) ? ((const float2*)hfin)[(g*128 + r)*32 + lane]
                                 : make_float2(0.f, 0.f);
            sy[t][2*lane]     = make_float2(v.x, v.x);
            sy[t][2*lane + 1] = make_float2(v.y, v.y);
        }
        __syncwarp();
        ull ya[4];
        #pragma unroll
        for (int t = 0; t < 4; ++t) ya[t] = b5p[lane];
        #pragma unroll 2
        for (int i = 0; i < 64; ++i) {
            ull a = ap[i*32 + lane];
            #pragma unroll
            for (int t = 0; t < 4; ++t) {
                ull xv = *(const ull*)&sy[t][i];
                ya[t] = ff2(a, xv, ya[t]);
            }
        }
        __syncwarp();
        #pragma unroll
        for (int t = 0; t < 4; ++t) {
            float2 y = up2(ya[t]);
            sy[t][2*lane]     = make_float2(y.x, y.x);
            sy[t][2*lane + 1] = make_float2(y.y, y.y);
        }
        __syncwarp();
        ull z01[4], z23[4];
        #pragma unroll
        for (int t = 0; t < 4; ++t) {
            z01[t] = pk2(sb1[4*lane], sb1[4*lane + 1]);
            z23[t] = pk2(sb1[4*lane + 2], sb1[4*lane + 3]);
        }
        #pragma unroll 2
        for (int k = 0; k < 64; ++k) {
            ulonglong2 wv = wp[k*32 + lane];
            #pragma unroll
            for (int t = 0; t < 4; ++t) {
                ull yy = *(const ull*)&sy[t][k];
                z01[t] = ff2(wv.x, yy, z01[t]);
                z23[t] = ff2(wv.y, yy, z23[t]);
            }
        }
        __syncwarp();
        float4 w2 = *(float4*)&sW2[4*lane];
        #pragma unroll
        for (int t = 0; t < 4; ++t) {
            float2 za = up2(z01[t]), zb = up2(z23[t]);
            float acc = fmaxf(za.x, 0.f)*w2.x + fmaxf(za.y, 0.f)*w2.y +
                        fmaxf(zb.x, 0.f)*w2.z + fmaxf(zb.y, 0.f)*w2.w;
            #pragma unroll
            for (int off = 16; off; off >>= 1)
                acc += __shfl_xor_sync(0xffffffffu, acc, off);
            int r = rbase + t;
            if (lane == 0 && r < 127) out[g*127 + r] = acc + bias2;
        }
    }
}

extern "C" void kernel_launch(void* const* d_in, const int* in_sizes, int n_in,
                              void* d_out, int out_size) {
    const float* x = (const float*)d_in[0];
    const void*  ei = d_in[1];
    int base = (in_sizes[3] == 1) ? 4 : 3;
    const float* W1  = (const float*)d_in[base + 0];
    const float* b1  = (const float*)d_in[base + 1];
    const float* W2  = (const float*)d_in[base + 2];
    const float* b2  = (const float*)d_in[base + 3];
    const float* W3  = (const float*)d_in[base + 4];
    const float* b3  = (const float*)d_in[base + 5];
    const float* W4  = (const float*)d_in[base + 6];
    const float* b4  = (const float*)d_in[base + 7];
    const float* W5  = (const float*)d_in[base + 8];
    const float* b5  = (const float*)d_in[base + 9];
    const float* Wd1 = (const float*)d_in[base + 10];
    const float* bd1 = (const float*)d_in[base + 11];
    const float* Wd2 = (const float*)d_in[base + 12];
    const float* bd2 = (const float*)d_in[base + 13];
    float* out = (float*)d_out;

    float *hA = nullptr, *hB = nullptr;
    cudaGetSymbolAddress((void**)&hA, g_h);
    cudaGetSymbolAddress((void**)&hB, g_m);

    cudaFuncSetAttribute(k_gup, cudaFuncAttributeMaxDynamicSharedMemorySize, 52*1024);
    cudaFuncSetAttribute(k_y1h, cudaFuncAttributeMaxDynamicSharedMemorySize, 72*1024);
    int gup_smem = 3072 * 16;                                 // 48KB
    int y1h_smem = (4096 + 8192 + 4096 + 64 + 128 + 128) * 4; // ~66KB

    k_pi<<<1553, 256>>>(x, ei, W1, b1, W2, b2, W3, b3, W4, b4);   // launch 1 (input + CSR fill)
    k_gup<<<592, 256, gup_smem>>>(hA, hB);                         // launch 2
    k_gup<<<592, 256, gup_smem>>>(hB, hA);                         // launch 3
    k_gup<<<592, 256, gup_smem>>>(hA, hB);                         // launch 4 <- ncu capture
    k_ag<<<256, 256>>>(W5, hB);                                    // launch 5
    k_y1h<<<GG, 256, y1h_smem>>>(hB, b5, Wd1, bd1, Wd2, bd2, out); // launch 6
}

// round 12
// speedup vs baseline: 1.8697x; 1.0116x over previous
#include <cuda_runtime.h>

#define NN 32768
#define GG 256
#define PP 128
#define EE 524288
#define HH 64
#define CAP 96
#define ROWS (GG*(PP-1))

typedef unsigned long long ull;

// ---- device scratch ----
__device__ __align__(16) float g_h[(NN+1)*HH];   // +1 sentinel zero row
__device__ __align__(16) float g_m[(NN+1)*HH];
__device__ __align__(16) float g_Ag[GG*HH*HH];
__device__ __align__(16) float g_AB[HH*HH*2];    // A table [0,4096), B table [4096,8192), k-pair packed
__device__ __align__(16) float g_c[HH];
__device__ __align__(16) int g_deg[NN];          // zeroed at end of k_ag each replay
__device__ int g_srcl[NN*CAP];

// ---- f32x2 helpers ----
__device__ __forceinline__ ull pk2(float x, float y) {
    ull r; asm("mov.b64 %0,{%1,%2};" : "=l"(r) : "f"(x), "f"(y)); return r;
}
__device__ __forceinline__ ull ff2(ull a, ull b, ull c) {
    ull d; asm("fma.rn.f32x2 %0,%1,%2,%3;" : "=l"(d) : "l"(a), "l"(b), "l"(c)); return d;
}
__device__ __forceinline__ ull ad2(ull a, ull b) {
    ull d; asm("add.rn.f32x2 %0,%1,%2;" : "=l"(d) : "l"(a), "l"(b)); return d;
}
__device__ __forceinline__ float2 up2(ull a) {
    float x, y; asm("mov.b64 {%0,%1},%2;" : "=f"(x), "=f"(y) : "l"(a));
    return make_float2(x, y);
}

// ---- launch 1: weights (blk 0-15), bias+sentinel (blk 16), input layer (17-528),
//                CSR bucket fill (blk 529-1552, overlapped) ----
__global__ void k_pi(const float* __restrict__ x, const void* __restrict__ ei,
                     const float* __restrict__ W1, const float* __restrict__ b1,
                     const float* __restrict__ W2, const float* __restrict__ b2,
                     const float* __restrict__ W3, const float* __restrict__ b3,
                     const float* __restrict__ W4, const float* __restrict__ b4) {
    int tid = threadIdx.x;
    if (blockIdx.x >= 529) {
        // ---- CSR fill, 2 edges/thread; local int64 detection (256 high-words) ----
        const int* ei32 = (const int*)ei;
        int bad = (ei32[2*tid + 1] != 0);
        int is64 = !__syncthreads_or(bad);
        int e = ((int)(blockIdx.x - 529)*256 + tid)*2;
        int s0, s1, d0, d1;
        if (is64) {
            longlong2 sv = *(const longlong2*)((const long long*)ei + e);
            longlong2 dv = *(const longlong2*)((const long long*)ei + EE + e);
            s0 = (int)sv.x; s1 = (int)sv.y; d0 = (int)dv.x; d1 = (int)dv.y;
        } else {
            int2 sv = *(const int2*)(ei32 + e);
            int2 dv = *(const int2*)(ei32 + EE + e);
            s0 = sv.x; s1 = sv.y; d0 = dv.x; d1 = dv.y;
        }
        int p0 = atomicAdd(&g_deg[d0], 1);
        g_srcl[d0*CAP + p0] = s0;
        int p1 = atomicAdd(&g_deg[d1], 1);
        g_srcl[d1*CAP + p1] = s1;
        return;
    }
    if (blockIdx.x < 16) {
        int e = blockIdx.x * 256 + tid;
        int o = e >> 6, k = e & 63;
        float a = 0.f, b = 0.f;
        for (int t = 0; t < 64; ++t) {
            a += W4[o*128 + t]      * W3[t*64 + k];
            b += W4[o*128 + 64 + t] * W2[t*64 + k];
        }
        // k-pair packed: float4 at (kp*32 + (o&31)) = {X[o][2kp],X[o][2kp+1],X[o+32][2kp],X[o+32][2kp+1]}
        int kp = k >> 1, ob = o & 31, comp = ((o >> 5) << 1) | (k & 1);
        g_AB[(kp*32 + ob)*4 + comp]        = a;
        g_AB[4096 + (kp*32 + ob)*4 + comp] = b;
        return;
    }
    if (blockIdx.x == 16) {
        if (tid < 64) {
            float c = b4[tid];
            for (int t = 0; t < 64; ++t)
                c += W4[tid*128 + t]*b3[t] + W4[tid*128 + 64 + t]*b2[t];
            g_c[tid] = c;
            g_h[NN*64 + tid] = 0.f;   // sentinel rows
            g_m[NN*64 + tid] = 0.f;
        }
        return;
    }
    // ---- input layer ----
    __shared__ __align__(16) float sW[8*64];
    __shared__ float sb[64];
    for (int e = tid; e < 512; e += 256) {
        int o = e >> 3, j = e & 7;
        sW[j*64 + o] = W1[e];
    }
    if (tid < 64) sb[tid] = b1[tid];
    __syncthreads();
    int lane = tid & 31, warp = tid >> 5;
    for (int node = (blockIdx.x - 17)*8 + warp; node < NN; node += 512*8) {
        float xv = (lane < 8) ? x[node*8 + lane] : 0.f;
        float a0 = sb[2*lane], a1 = sb[2*lane + 1];
        #pragma unroll
        for (int j = 0; j < 8; ++j) {
            float xj = __shfl_sync(0xffffffffu, xv, j);
            a0 += sW[j*64 + 2*lane]     * xj;
            a1 += sW[j*64 + 2*lane + 1] * xj;
        }
        a0 = fmaxf(a0, 0.f); a1 = fmaxf(a1, 0.f);
        float s = a0*a0 + a1*a1;
        #pragma unroll
        for (int off = 16; off; off >>= 1) s += __shfl_xor_sync(0xffffffffu, s, off);
        float rn = rsqrtf(s);
        ((float2*)g_h)[node*32 + lane] = make_float2(a0*rn, a1*rn);
    }
}

// ---- launches 2-4: gather + update, 4 nodes/warp, 512 thr, 2 blocks/SM (R10 measured optimum) ----
__global__ void __launch_bounds__(512, 2)
k_gup(const float* __restrict__ hin, float* __restrict__ hout) {
    extern __shared__ __align__(16) float4 dynsm[];
    float4* sWA = dynsm;          // 1024 float4 = 16KB : A[kp][o-pair packed]
    float4* sWB = dynsm + 1024;   // 1024 float4 = 16KB
    ulonglong2* sX = (ulonglong2*)(dynsm + 2048);  // 16 warps * 4 nodes * 32 kp = 32KB
    int tid = threadIdx.x;
    for (int e = tid; e < 2048; e += 512) {
        sWA[e] = ((const float4*)g_AB)[e];          // first 1024: A, next 1024: B
    }
    __syncthreads();
    int lane = tid & 31, warp = tid >> 5;
    ulonglong2* myX = sX + warp*128;
    ull cinit0 = pk2(g_c[lane], 0.f);
    ull cinit1 = pk2(g_c[32 + lane], 0.f);
    int nb = (blockIdx.x*16 + warp)*4;
    const ull* hin64 = (const ull*)hin;

    // ---- gather phase: prefetch degs + first index vectors for all 4 nodes ----
    int deg[4], idx[4];
    #pragma unroll
    for (int t = 0; t < 4; ++t) deg[t] = g_deg[nb + t];
    #pragma unroll
    for (int t = 0; t < 4; ++t) {
        int n = deg[t] < 32 ? deg[t] : 32;
        idx[t] = (lane < n) ? g_srcl[(nb + t)*CAP + lane] : NN;
    }
    #pragma unroll
    for (int t = 0; t < 4; ++t) {
        int n = deg[t] < 32 ? deg[t] : 32;
        ull m0 = 0ULL, m1 = 0ULL;   // f32x2 accumulators (0.0f bits)
        int nr = (n + 7) & ~7;
        #pragma unroll 8
        for (int j = 0; j < nr; j += 2) {
            int sa = __shfl_sync(0xffffffffu, idx[t], j);
            int sb = __shfl_sync(0xffffffffu, idx[t], j + 1);
            m0 = ad2(m0, hin64[sa*32 + lane]);
            m1 = ad2(m1, hin64[sb*32 + lane]);
        }
        // rare tail (deg > 32)
        for (int b = 32; b < deg[t]; b += 32) {
            int nn = deg[t] - b; if (nn > 32) nn = 32;
            int id2 = (lane < nn) ? g_srcl[(nb + t)*CAP + b + lane] : NN;
            for (int j = 0; j < nn; ++j) {
                int s = __shfl_sync(0xffffffffu, id2, j);
                m0 = ad2(m0, hin64[s*32 + lane]);
            }
        }
        ull mv = ad2(m0, m1);
        ull hv = hin64[(nb + t)*32 + lane];
        myX[t*32 + lane] = make_ulonglong2(mv, hv);   // (m-pair, h-pair) for kp=lane
    }
    __syncwarp();

    // ---- GEMM phase: acc over k-pairs; outputs o=lane, o=lane+32 ----
    ull acc0[4], acc1[4];
    #pragma unroll
    for (int t = 0; t < 4; ++t) { acc0[t] = cinit0; acc1[t] = cinit1; }
    const ulonglong2* wa = (const ulonglong2*)sWA;
    const ulonglong2* wb = (const ulonglong2*)sWB;
    #pragma unroll
    for (int kp = 0; kp < 32; ++kp) {
        ulonglong2 A = wa[kp*32 + lane];   // .x: (A[o][2kp],A[o][2kp+1])  .y: o+32
        ulonglong2 B = wb[kp*32 + lane];
        #pragma unroll
        for (int t = 0; t < 4; ++t) {
            ulonglong2 xv = myX[t*32 + kp]; // broadcast: .x = m-pair, .y = h-pair
            acc0[t] = ff2(A.x, xv.x, acc0[t]);
            acc0[t] = ff2(B.x, xv.y, acc0[t]);
            acc1[t] = ff2(A.y, xv.x, acc1[t]);
            acc1[t] = ff2(B.y, xv.y, acc1[t]);
        }
    }
    // ---- epilogue ----
    float alo[4], ahi[4], s[4];
    #pragma unroll
    for (int t = 0; t < 4; ++t) {
        float2 p0 = up2(acc0[t]), p1 = up2(acc1[t]);
        alo[t] = fmaxf(p0.x + p0.y, 0.f);
        ahi[t] = fmaxf(p1.x + p1.y, 0.f);
        s[t] = alo[t]*alo[t] + ahi[t]*ahi[t];
    }
    #pragma unroll
    for (int off = 16; off; off >>= 1) {
        #pragma unroll
        for (int t = 0; t < 4; ++t) s[t] += __shfl_xor_sync(0xffffffffu, s[t], off);
    }
    #pragma unroll
    for (int t = 0; t < 4; ++t) {
        float rn = rsqrtf(s[t]);
        hout[(nb + t)*64 + lane]      = alo[t]*rn;
        hout[(nb + t)*64 + 32 + lane] = ahi[t]*rn;
    }
}

// ---- launch 5: Ag, 256 blocks (o x graph-chunk), 4 graphs/warp/pass; also zero g_deg ----
__global__ void k_ag(const float* __restrict__ W5, const float* __restrict__ hfin) {
    __shared__ __align__(16) float sWT[4096];     // [j][i]
    __shared__ __align__(16) float2 sL[8][4][64];
    int bi = blockIdx.x, tid = threadIdx.x;
    int o = bi >> 2, gc = bi & 3;
    if (tid < 128) g_deg[bi*128 + tid] = 0;       // reset cursors for next replay
    for (int e = tid; e < 4096; e += 256) {
        int i = e >> 6, j = e & 63;
        sWT[j*64 + i] = W5[o*4096 + e];
    }
    __syncthreads();
    int lane = tid & 31, warp = tid >> 5;
    const ull* wp = (const ull*)sWT;
    for (int pass = 0; pass < 2; ++pass) {
        int gbase = gc*64 + pass*32 + warp*4;
        #pragma unroll
        for (int t = 0; t < 4; ++t) {
            int g = gbase + t;
            float2 v = ((const float2*)hfin)[(g*128 + 127)*32 + lane];
            sL[warp][t][2*lane]     = make_float2(v.x, v.x);
            sL[warp][t][2*lane + 1] = make_float2(v.y, v.y);
        }
        __syncwarp();
        ull acc[4] = {0ULL, 0ULL, 0ULL, 0ULL};
        #pragma unroll 2
        for (int j = 0; j < 64; ++j) {
            ull w = wp[j*32 + lane];
            #pragma unroll
            for (int t = 0; t < 4; ++t) {
                ull xv = *(const ull*)&sL[warp][t][j];
                acc[t] = ff2(w, xv, acc[t]);
            }
        }
        __syncwarp();
        #pragma unroll
        for (int t = 0; t < 4; ++t) {
            int g = gbase + t;
            ((float2*)(g_Ag + g*4096 + o*64))[lane] = up2(acc[t]);
        }
    }
}

// ---- launch 6: fused y1 + head, 4 rows/warp/pass ----
__global__ void k_y1h(const float* __restrict__ hfin, const float* __restrict__ b5,
                      const float* __restrict__ Wd1, const float* __restrict__ bd1,
                      const float* __restrict__ Wd2, const float* __restrict__ bd2,
                      float* __restrict__ out) {
    extern __shared__ __align__(16) float dyn[];
    float*  sAgT = dyn;                   // 4096 [i][o]
    float*  sW1T = dyn + 4096;            // 8192 [k][j]
    float2* sY   = (float2*)(dyn + 4096 + 8192);  // 8*4*64 float2
    float*  sb5  = dyn + 4096 + 8192 + 4096;
    float*  sb1  = sb5 + 64;
    float*  sW2  = sb1 + 128;
    int g = blockIdx.x, tid = threadIdx.x;
    for (int e = tid; e < 4096; e += 256) {
        int o = e & 63, i = e >> 6;
        sAgT[i*64 + o] = g_Ag[g*4096 + o*64 + i];
    }
    for (int e = tid; e < 8192; e += 256) {
        int j = e >> 6, k = e & 63;
        sW1T[k*128 + j] = Wd1[e];
    }
    if (tid < 64) sb5[tid] = b5[tid];
    if (tid < 128) { sb1[tid] = bd1[tid]; sW2[tid] = Wd2[tid]; }
    __syncthreads();
    float bias2 = bd2[0];
    int lane = tid & 31, warp = tid >> 5;
    float2 (*sy)[64] = (float2 (*)[64])(sY + warp*256);
    const ull* ap = (const ull*)sAgT;
    const ulonglong2* wp = (const ulonglong2*)sW1T;
    const ull* b5p = (const ull*)sb5;
    for (int pass = 0; pass < 4; ++pass) {
        int rbase = pass*32 + warp*4;
        #pragma unroll
        for (int t = 0; t < 4; ++t) {
            int r = rbase + t;
            float2 v = (r < 127) ? ((const float2*)hfin)[(g*128 + r)*32 + lane]
                                 : make_float2(0.f, 0.f);
            sy[t][2*lane]     = make_float2(v.x, v.x);
            sy[t][2*lane + 1] = make_float2(v.y, v.y);
        }
        __syncwarp();
        ull ya[4];
        #pragma unroll
        for (int t = 0; t < 4; ++t) ya[t] = b5p[lane];
        #pragma unroll 2
        for (int i = 0; i < 64; ++i) {
            ull a = ap[i*32 + lane];
            #pragma unroll
            for (int t = 0; t < 4; ++t) {
                ull xv = *(const ull*)&sy[t][i];
                ya[t] = ff2(a, xv, ya[t]);
            }
        }
        __syncwarp();
        #pragma unroll
        for (int t = 0; t < 4; ++t) {
            float2 y = up2(ya[t]);
            sy[t][2*lane]     = make_float2(y.x, y.x);
            sy[t][2*lane + 1] = make_float2(y.y, y.y);
        }
        __syncwarp();
        ull z01[4], z23[4];
        #pragma unroll
        for (int t = 0; t < 4; ++t) {
            z01[t] = pk2(sb1[4*lane], sb1[4*lane + 1]);
            z23[t] = pk2(sb1[4*lane + 2], sb1[4*lane + 3]);
        }
        #pragma unroll 2
        for (int k = 0; k < 64; ++k) {
            ulonglong2 wv = wp[k*32 + lane];
            #pragma unroll
            for (int t = 0; t < 4; ++t) {
                ull yy = *(const ull*)&sy[t][k];
                z01[t] = ff2(wv.x, yy, z01[t]);
                z23[t] = ff2(wv.y, yy, z23[t]);
            }
        }
        __syncwarp();
        float4 w2 = *(float4*)&sW2[4*lane];
        #pragma unroll
        for (int t = 0; t < 4; ++t) {
            float2 za = up2(z01[t]), zb = up2(z23[t]);
            float acc = fmaxf(za.x, 0.f)*w2.x + fmaxf(za.y, 0.f)*w2.y +
                        fmaxf(zb.x, 0.f)*w2.z + fmaxf(zb.y, 0.f)*w2.w;
            #pragma unroll
            for (int off = 16; off; off >>= 1)
                acc += __shfl_xor_sync(0xffffffffu, acc, off);
            int r = rbase + t;
            if (lane == 0 && r < 127) out[g*127 + r] = acc + bias2;
        }
    }
}

extern "C" void kernel_launch(void* const* d_in, const int* in_sizes, int n_in,
                              void* d_out, int out_size) {
    const float* x = (const float*)d_in[0];
    const void*  ei = d_in[1];
    int base = (in_sizes[3] == 1) ? 4 : 3;
    const float* W1  = (const float*)d_in[base + 0];
    const float* b1  = (const float*)d_in[base + 1];
    const float* W2  = (const float*)d_in[base + 2];
    const float* b2  = (const float*)d_in[base + 3];
    const float* W3  = (const float*)d_in[base + 4];
    const float* b3  = (const float*)d_in[base + 5];
    const float* W4  = (const float*)d_in[base + 6];
    const float* b4  = (const float*)d_in[base + 7];
    const float* W5  = (const float*)d_in[base + 8];
    const float* b5  = (const float*)d_in[base + 9];
    const float* Wd1 = (const float*)d_in[base + 10];
    const float* bd1 = (const float*)d_in[base + 11];
    const float* Wd2 = (const float*)d_in[base + 12];
    const float* bd2 = (const float*)d_in[base + 13];
    float* out = (float*)d_out;

    float *hA = nullptr, *hB = nullptr;
    cudaGetSymbolAddress((void**)&hA, g_h);
    cudaGetSymbolAddress((void**)&hB, g_m);

    cudaFuncSetAttribute(k_gup, cudaFuncAttributeMaxDynamicSharedMemorySize, 72*1024);
    cudaFuncSetAttribute(k_y1h, cudaFuncAttributeMaxDynamicSharedMemorySize, 72*1024);
    int gup_smem = 4096 * 16;                                 // 64KB
    int y1h_smem = (4096 + 8192 + 4096 + 64 + 128 + 128) * 4; // ~66KB

    k_pi<<<1553, 256>>>(x, ei, W1, b1, W2, b2, W3, b3, W4, b4);   // launch 1 (input + CSR fill)
    k_gup<<<NN/64, 512, gup_smem>>>(hA, hB);                       // launch 2
    k_gup<<<NN/64, 512, gup_smem>>>(hB, hA);                       // launch 3
    k_gup<<<NN/64, 512, gup_smem>>>(hA, hB);                       // launch 4 <- ncu capture
    k_ag<<<256, 256>>>(W5, hB);                                    // launch 5
    k_y1h<<<GG, 256, y1h_smem>>>(hB, b5, Wd1, bd1, Wd2, bd2, out); // launch 6
}

// round 13
// speedup vs baseline: 1.8928x; 1.0123x over previous
#include <cuda_runtime.h>

#define NN 32768
#define GG 256
#define PP 128
#define EE 524288
#define HH 64
#define CAP 96
#define ROWS (GG*(PP-1))

typedef unsigned long long ull;

// ---- device scratch ----
__device__ __align__(16) float g_h[(NN+1)*HH];   // +1 sentinel zero row
__device__ __align__(16) float g_m[(NN+1)*HH];
__device__ __align__(16) float g_s[NN*HH];       // gathered messages scratch
__device__ __align__(16) float g_Ag[GG*HH*HH];
__device__ __align__(16) float g_AB[HH*HH*2];    // A table [0,4096), B table [4096,8192), k-pair packed
__device__ __align__(16) float g_c[HH];
__device__ __align__(16) int g_deg[NN];          // zeroed at end of k_ag each replay
__device__ int g_srcl[NN*CAP];

// ---- f32x2 helpers ----
__device__ __forceinline__ ull pk2(float x, float y) {
    ull r; asm("mov.b64 %0,{%1,%2};" : "=l"(r) : "f"(x), "f"(y)); return r;
}
__device__ __forceinline__ ull ff2(ull a, ull b, ull c) {
    ull d; asm("fma.rn.f32x2 %0,%1,%2,%3;" : "=l"(d) : "l"(a), "l"(b), "l"(c)); return d;
}
__device__ __forceinline__ ull ad2(ull a, ull b) {
    ull d; asm("add.rn.f32x2 %0,%1,%2;" : "=l"(d) : "l"(a), "l"(b)); return d;
}
__device__ __forceinline__ float2 up2(ull a) {
    float x, y; asm("mov.b64 {%0,%1},%2;" : "=f"(x), "=f"(y) : "l"(a));
    return make_float2(x, y);
}

// ---- launch 1: weights (blk 0-15), bias+sentinel (blk 16), input layer (17-528),
//                CSR bucket fill (blk 529-1552, overlapped) ----
__global__ void k_pi(const float* __restrict__ x, const void* __restrict__ ei,
                     const float* __restrict__ W1, const float* __restrict__ b1,
                     const float* __restrict__ W2, const float* __restrict__ b2,
                     const float* __restrict__ W3, const float* __restrict__ b3,
                     const float* __restrict__ W4, const float* __restrict__ b4) {
    int tid = threadIdx.x;
    if (blockIdx.x >= 529) {
        // ---- CSR fill, 2 edges/thread; local int64 detection (256 high-words) ----
        const int* ei32 = (const int*)ei;
        int bad = (ei32[2*tid + 1] != 0);
        int is64 = !__syncthreads_or(bad);
        int e = ((int)(blockIdx.x - 529)*256 + tid)*2;
        int s0, s1, d0, d1;
        if (is64) {
            longlong2 sv = *(const longlong2*)((const long long*)ei + e);
            longlong2 dv = *(const longlong2*)((const long long*)ei + EE + e);
            s0 = (int)sv.x; s1 = (int)sv.y; d0 = (int)dv.x; d1 = (int)dv.y;
        } else {
            int2 sv = *(const int2*)(ei32 + e);
            int2 dv = *(const int2*)(ei32 + EE + e);
            s0 = sv.x; s1 = sv.y; d0 = dv.x; d1 = dv.y;
        }
        int p0 = atomicAdd(&g_deg[d0], 1);
        g_srcl[d0*CAP + p0] = s0;
        int p1 = atomicAdd(&g_deg[d1], 1);
        g_srcl[d1*CAP + p1] = s1;
        return;
    }
    if (blockIdx.x < 16) {
        int e = blockIdx.x * 256 + tid;
        int o = e >> 6, k = e & 63;
        float a = 0.f, b = 0.f;
        for (int t = 0; t < 64; ++t) {
            a += W4[o*128 + t]      * W3[t*64 + k];
            b += W4[o*128 + 64 + t] * W2[t*64 + k];
        }
        // k-pair packed: float4 at (kp*32 + (o&31)) = {X[o][2kp],X[o][2kp+1],X[o+32][2kp],X[o+32][2kp+1]}
        int kp = k >> 1, ob = o & 31, comp = ((o >> 5) << 1) | (k & 1);
        g_AB[(kp*32 + ob)*4 + comp]        = a;
        g_AB[4096 + (kp*32 + ob)*4 + comp] = b;
        return;
    }
    if (blockIdx.x == 16) {
        if (tid < 64) {
            float c = b4[tid];
            for (int t = 0; t < 64; ++t)
                c += W4[tid*128 + t]*b3[t] + W4[tid*128 + 64 + t]*b2[t];
            g_c[tid] = c;
            g_h[NN*64 + tid] = 0.f;   // sentinel rows
            g_m[NN*64 + tid] = 0.f;
        }
        return;
    }
    // ---- input layer ----
    __shared__ __align__(16) float sW[8*64];
    __shared__ float sb[64];
    for (int e = tid; e < 512; e += 256) {
        int o = e >> 3, j = e & 7;
        sW[j*64 + o] = W1[e];
    }
    if (tid < 64) sb[tid] = b1[tid];
    __syncthreads();
    int lane = tid & 31, warp = tid >> 5;
    for (int node = (blockIdx.x - 17)*8 + warp; node < NN; node += 512*8) {
        float xv = (lane < 8) ? x[node*8 + lane] : 0.f;
        float a0 = sb[2*lane], a1 = sb[2*lane + 1];
        #pragma unroll
        for (int j = 0; j < 8; ++j) {
            float xj = __shfl_sync(0xffffffffu, xv, j);
            a0 += sW[j*64 + 2*lane]     * xj;
            a1 += sW[j*64 + 2*lane + 1] * xj;
        }
        a0 = fmaxf(a0, 0.f); a1 = fmaxf(a1, 0.f);
        float s = a0*a0 + a1*a1;
        #pragma unroll
        for (int off = 16; off; off >>= 1) s += __shfl_xor_sync(0xffffffffu, s, off);
        float rn = rsqrtf(s);
        ((float2*)g_h)[node*32 + lane] = make_float2(a0*rn, a1*rn);
    }
}

// ---- pure gather: m[node] = sum_{src in N(node)} hin[src]; 4 nodes/warp, no smem ----
__global__ void __launch_bounds__(512)
k_gat(const float* __restrict__ hin, float* __restrict__ mout) {
    int tid = threadIdx.x;
    int lane = tid & 31, warp = tid >> 5;
    int nb = (blockIdx.x*16 + warp)*4;
    const ull* hin64 = (const ull*)hin;
    ull* mout64 = (ull*)mout;
    int deg[4], idx[4];
    #pragma unroll
    for (int t = 0; t < 4; ++t) deg[t] = g_deg[nb + t];
    #pragma unroll
    for (int t = 0; t < 4; ++t) {
        int n = deg[t] < 32 ? deg[t] : 32;
        idx[t] = (lane < n) ? g_srcl[(nb + t)*CAP + lane] : NN;
    }
    #pragma unroll
    for (int t = 0; t < 4; ++t) {
        int n = deg[t] < 32 ? deg[t] : 32;
        ull m0 = 0ULL, m1 = 0ULL;
        int nr = (n + 7) & ~7;
        #pragma unroll 8
        for (int j = 0; j < nr; j += 2) {
            int sa = __shfl_sync(0xffffffffu, idx[t], j);
            int sb = __shfl_sync(0xffffffffu, idx[t], j + 1);
            m0 = ad2(m0, hin64[sa*32 + lane]);
            m1 = ad2(m1, hin64[sb*32 + lane]);
        }
        for (int b = 32; b < deg[t]; b += 32) {   // rare tail (deg > 32)
            int nn = deg[t] - b; if (nn > 32) nn = 32;
            int id2 = (lane < nn) ? g_srcl[(nb + t)*CAP + b + lane] : NN;
            for (int j = 0; j < nn; ++j) {
                int s = __shfl_sync(0xffffffffu, id2, j);
                m0 = ad2(m0, hin64[s*32 + lane]);
            }
        }
        mout64[(nb + t)*32 + lane] = ad2(m0, m1);
    }
}

// ---- dense update: hout = normalize(relu(A@m + B@h + c)); 8 nodes/warp, weight-amortized ----
__global__ void __launch_bounds__(256, 3)
k_up(const float* __restrict__ hin, const float* __restrict__ min,
     float* __restrict__ hout) {
    extern __shared__ __align__(16) float4 dynsm[];
    float4* sWA = dynsm;          // 1024 float4 = 16KB
    float4* sWB = dynsm + 1024;   // 1024 float4 = 16KB
    ulonglong2* sX = (ulonglong2*)(dynsm + 2048);  // 8 warps * 8 nodes * 32 kp = 32KB
    int tid = threadIdx.x;
    for (int e = tid; e < 2048; e += 256) sWA[e] = ((const float4*)g_AB)[e];
    __syncthreads();
    int lane = tid & 31, warp = tid >> 5;
    ulonglong2* myX = sX + warp*256;
    ull cinit0 = pk2(g_c[lane], 0.f);
    ull cinit1 = pk2(g_c[32 + lane], 0.f);
    int nb = (blockIdx.x*8 + warp)*8;
    const ull* hin64 = (const ull*)hin;
    const ull* min64 = (const ull*)min;

    #pragma unroll
    for (int t = 0; t < 8; ++t) {
        ull mv = min64[(nb + t)*32 + lane];
        ull hv = hin64[(nb + t)*32 + lane];
        myX[t*32 + lane] = make_ulonglong2(mv, hv);
    }
    __syncwarp();

    ull acc0[8], acc1[8];
    #pragma unroll
    for (int t = 0; t < 8; ++t) { acc0[t] = cinit0; acc1[t] = cinit1; }
    const ulonglong2* wa = (const ulonglong2*)sWA;
    const ulonglong2* wb = (const ulonglong2*)sWB;
    #pragma unroll 4
    for (int kp = 0; kp < 32; ++kp) {
        ulonglong2 A = wa[kp*32 + lane];
        ulonglong2 B = wb[kp*32 + lane];
        #pragma unroll
        for (int t = 0; t < 8; ++t) {
            ulonglong2 xv = myX[t*32 + kp];  // broadcast
            acc0[t] = ff2(A.x, xv.x, acc0[t]);
            acc0[t] = ff2(B.x, xv.y, acc0[t]);
            acc1[t] = ff2(A.y, xv.x, acc1[t]);
            acc1[t] = ff2(B.y, xv.y, acc1[t]);
        }
    }
    float alo[8], ahi[8], s[8];
    #pragma unroll
    for (int t = 0; t < 8; ++t) {
        float2 p0 = up2(acc0[t]), p1 = up2(acc1[t]);
        alo[t] = fmaxf(p0.x + p0.y, 0.f);
        ahi[t] = fmaxf(p1.x + p1.y, 0.f);
        s[t] = alo[t]*alo[t] + ahi[t]*ahi[t];
    }
    #pragma unroll
    for (int off = 16; off; off >>= 1) {
        #pragma unroll
        for (int t = 0; t < 8; ++t) s[t] += __shfl_xor_sync(0xffffffffu, s[t], off);
    }
    #pragma unroll
    for (int t = 0; t < 8; ++t) {
        float rn = rsqrtf(s[t]);
        hout[(nb + t)*64 + lane]      = alo[t]*rn;
        hout[(nb + t)*64 + 32 + lane] = ahi[t]*rn;
    }
}

// ---- Ag, 256 blocks (o x graph-chunk), 4 graphs/warp/pass; also zero g_deg ----
__global__ void k_ag(const float* __restrict__ W5, const float* __restrict__ hfin) {
    __shared__ __align__(16) float sWT[4096];     // [j][i]
    __shared__ __align__(16) float2 sL[8][4][64];
    int bi = blockIdx.x, tid = threadIdx.x;
    int o = bi >> 2, gc = bi & 3;
    if (tid < 128) g_deg[bi*128 + tid] = 0;       // reset cursors for next replay
    for (int e = tid; e < 4096; e += 256) {
        int i = e >> 6, j = e & 63;
        sWT[j*64 + i] = W5[o*4096 + e];
    }
    __syncthreads();
    int lane = tid & 31, warp = tid >> 5;
    const ull* wp = (const ull*)sWT;
    for (int pass = 0; pass < 2; ++pass) {
        int gbase = gc*64 + pass*32 + warp*4;
        #pragma unroll
        for (int t = 0; t < 4; ++t) {
            int g = gbase + t;
            float2 v = ((const float2*)hfin)[(g*128 + 127)*32 + lane];
            sL[warp][t][2*lane]     = make_float2(v.x, v.x);
            sL[warp][t][2*lane + 1] = make_float2(v.y, v.y);
        }
        __syncwarp();
        ull acc[4] = {0ULL, 0ULL, 0ULL, 0ULL};
        #pragma unroll 2
        for (int j = 0; j < 64; ++j) {
            ull w = wp[j*32 + lane];
            #pragma unroll
            for (int t = 0; t < 4; ++t) {
                ull xv = *(const ull*)&sL[warp][t][j];
                acc[t] = ff2(w, xv, acc[t]);
            }
        }
        __syncwarp();
        #pragma unroll
        for (int t = 0; t < 4; ++t) {
            int g = gbase + t;
            ((float2*)(g_Ag + g*4096 + o*64))[lane] = up2(acc[t]);
        }
    }
}

// ---- fused y1 + head, 4 rows/warp/pass ----
__global__ void k_y1h(const float* __restrict__ hfin, const float* __restrict__ b5,
                      const float* __restrict__ Wd1, const float* __restrict__ bd1,
                      const float* __restrict__ Wd2, const float* __restrict__ bd2,
                      float* __restrict__ out) {
    extern __shared__ __align__(16) float dyn[];
    float*  sAgT = dyn;                   // 4096 [i][o]
    float*  sW1T = dyn + 4096;            // 8192 [k][j]
    float2* sY   = (float2*)(dyn + 4096 + 8192);  // 8*4*64 float2
    float*  sb5  = dyn + 4096 + 8192 + 4096;
    float*  sb1  = sb5 + 64;
    float*  sW2  = sb1 + 128;
    int g = blockIdx.x, tid = threadIdx.x;
    for (int e = tid; e < 4096; e += 256) {
        int o = e & 63, i = e >> 6;
        sAgT[i*64 + o] = g_Ag[g*4096 + o*64 + i];
    }
    for (int e = tid; e < 8192; e += 256) {
        int j = e >> 6, k = e & 63;
        sW1T[k*128 + j] = Wd1[e];
    }
    if (tid < 64) sb5[tid] = b5[tid];
    if (tid < 128) { sb1[tid] = bd1[tid]; sW2[tid] = Wd2[tid]; }
    __syncthreads();
    float bias2 = bd2[0];
    int lane = tid & 31, warp = tid >> 5;
    float2 (*sy)[64] = (float2 (*)[64])(sY + warp*256);
    const ull* ap = (const ull*)sAgT;
    const ulonglong2* wp = (const ulonglong2*)sW1T;
    const ull* b5p = (const ull*)sb5;
    for (int pass = 0; pass < 4; ++pass) {
        int rbase = pass*32 + warp*4;
        #pragma unroll
        for (int t = 0; t < 4; ++t) {
            int r = rbase + t;
            float2 v = (r < 127) ? ((const float2*)hfin)[(g*128 + r)*32 + lane]
                                 : make_float2(0.f, 0.f);
            sy[t][2*lane]     = make_float2(v.x, v.x);
            sy[t][2*lane + 1] = make_float2(v.y, v.y);
        }
        __syncwarp();
        ull ya[4];
        #pragma unroll
        for (int t = 0; t < 4; ++t) ya[t] = b5p[lane];
        #pragma unroll 2
        for (int i = 0; i < 64; ++i) {
            ull a = ap[i*32 + lane];
            #pragma unroll
            for (int t = 0; t < 4; ++t) {
                ull xv = *(const ull*)&sy[t][i];
                ya[t] = ff2(a, xv, ya[t]);
            }
        }
        __syncwarp();
        #pragma unroll
        for (int t = 0; t < 4; ++t) {
            float2 y = up2(ya[t]);
            sy[t][2*lane]     = make_float2(y.x, y.x);
            sy[t][2*lane + 1] = make_float2(y.y, y.y);
        }
        __syncwarp();
        ull z01[4], z23[4];
        #pragma unroll
        for (int t = 0; t < 4; ++t) {
            z01[t] = pk2(sb1[4*lane], sb1[4*lane + 1]);
            z23[t] = pk2(sb1[4*lane + 2], sb1[4*lane + 3]);
        }
        #pragma unroll 2
        for (int k = 0; k < 64; ++k) {
            ulonglong2 wv = wp[k*32 + lane];
            #pragma unroll
            for (int t = 0; t < 4; ++t) {
                ull yy = *(const ull*)&sy[t][k];
                z01[t] = ff2(wv.x, yy, z01[t]);
                z23[t] = ff2(wv.y, yy, z23[t]);
            }
        }
        __syncwarp();
        float4 w2 = *(float4*)&sW2[4*lane];
        #pragma unroll
        for (int t = 0; t < 4; ++t) {
            float2 za = up2(z01[t]), zb = up2(z23[t]);
            float acc = fmaxf(za.x, 0.f)*w2.x + fmaxf(za.y, 0.f)*w2.y +
                        fmaxf(zb.x, 0.f)*w2.z + fmaxf(zb.y, 0.f)*w2.w;
            #pragma unroll
            for (int off = 16; off; off >>= 1)
                acc += __shfl_xor_sync(0xffffffffu, acc, off);
            int r = rbase + t;
            if (lane == 0 && r < 127) out[g*127 + r] = acc + bias2;
        }
    }
}

extern "C" void kernel_launch(void* const* d_in, const int* in_sizes, int n_in,
                              void* d_out, int out_size) {
    const float* x = (const float*)d_in[0];
    const void*  ei = d_in[1];
    int base = (in_sizes[3] == 1) ? 4 : 3;
    const float* W1  = (const float*)d_in[base + 0];
    const float* b1  = (const float*)d_in[base + 1];
    const float* W2  = (const float*)d_in[base + 2];
    const float* b2  = (const float*)d_in[base + 3];
    const float* W3  = (const float*)d_in[base + 4];
    const float* b3  = (const float*)d_in[base + 5];
    const float* W4  = (const float*)d_in[base + 6];
    const float* b4  = (const float*)d_in[base + 7];
    const float* W5  = (const float*)d_in[base + 8];
    const float* b5  = (const float*)d_in[base + 9];
    const float* Wd1 = (const float*)d_in[base + 10];
    const float* bd1 = (const float*)d_in[base + 11];
    const float* Wd2 = (const float*)d_in[base + 12];
    const float* bd2 = (const float*)d_in[base + 13];
    float* out = (float*)d_out;

    float *hA = nullptr, *hB = nullptr, *ms = nullptr;
    cudaGetSymbolAddress((void**)&hA, g_h);
    cudaGetSymbolAddress((void**)&hB, g_m);
    cudaGetSymbolAddress((void**)&ms, g_s);

    cudaFuncSetAttribute(k_up,  cudaFuncAttributeMaxDynamicSharedMemorySize, 72*1024);
    cudaFuncSetAttribute(k_y1h, cudaFuncAttributeMaxDynamicSharedMemorySize, 72*1024);
    int up_smem  = 4096 * 16;                                 // 64KB
    int y1h_smem = (4096 + 8192 + 4096 + 64 + 128 + 128) * 4; // ~66KB

    k_pi<<<1553, 256>>>(x, ei, W1, b1, W2, b2, W3, b3, W4, b4);   // 1: input + CSR fill
    k_gat<<<NN/64, 512>>>(hA, ms);                                 // 2: gather d0
    k_up<<<NN/64, 256, up_smem>>>(hA, ms, hB);                     // 3: update d0
    k_gat<<<NN/64, 512>>>(hB, ms);                                 // 4: gather d1 <- ncu capture
    k_up<<<NN/64, 256, up_smem>>>(hB, ms, hA);                     // 5: update d1
    k_gat<<<NN/64, 512>>>(hA, ms);                                 // 6: gather d2
    k_up<<<NN/64, 256, up_smem>>>(hA, ms, hB);                     // 7: update d2
    k_ag<<<256, 256>>>(W5, hB);                                    // 8
    k_y1h<<<GG, 256, y1h_smem>>>(hB, b5, Wd1, bd1, Wd2, bd2, out); // 9
}